// round 8
// baseline (speedup 1.0000x reference)
#include <cuda_runtime.h>
#include <math.h>
#include <stdint.h>
#include <stddef.h>

#define Bb 128
#define Ss 256
#define Ii 256
#define Hh 1024
#define Oo 256
#define NBLK 128

// ------------------------- f32x2 packed-FMA helpers (sm_103a) -------------------
__device__ __forceinline__ unsigned long long pack2(float lo, float hi) {
    unsigned long long d;
    asm("mov.b64 %0, {%1, %2};" : "=l"(d) : "r"(__float_as_uint(lo)), "r"(__float_as_uint(hi)));
    return d;
}
__device__ __forceinline__ float2 unpack2(unsigned long long v) {
    unsigned int lo, hi;
    asm("mov.b64 {%0, %1}, %2;" : "=r"(lo), "=r"(hi) : "l"(v));
    return make_float2(__uint_as_float(lo), __uint_as_float(hi));
}
__device__ __forceinline__ unsigned long long ffma2(
    unsigned long long a, unsigned long long b, unsigned long long c) {
    unsigned long long d;
    asm("fma.rn.f32x2 %0, %1, %2, %3;" : "=l"(d) : "l"(a), "l"(b), "l"(c));
    return d;
}

// ------------------------- device scratch (no allocations allowed) -------------
__device__ float g_xz[Ss * Bb];
__device__ float g_xr[Ss * Bb];
__device__ float g_xg[(size_t)Ss * Bb * Hh];   // 128 MB
__device__ float g_hs[(size_t)Ss * Bb * Hh];   // 128 MB
__device__ float g_ht[2][Hh * Bb];             // hidden state, k-major [k][b], dbl buf
__device__ unsigned g_bar_count;
__device__ volatile unsigned g_bar_gen;

// ------------------------- grid barrier (all NBLK CTAs resident) ---------------
__device__ __forceinline__ void grid_barrier() {
    __syncthreads();
    if (threadIdx.x == 0) {
        __threadfence();
        unsigned gen = g_bar_gen;
        unsigned t = atomicAdd(&g_bar_count, 1u);
        if (t == gridDim.x - 1) {
            g_bar_count = 0;
            __threadfence();
            g_bar_gen = gen + 1u;
        } else {
            while (g_bar_gen == gen) { __nanosleep(32); }
        }
        __threadfence();
    }
    __syncthreads();
}

// ------------------------- scalar-gate projections ----------------------------
__global__ void __launch_bounds__(256) proj_zr(
    const float* __restrict__ A, const float* __restrict__ Wxz,
    const float* __restrict__ Wxr, const float* __restrict__ bxr,
    float* __restrict__ xz, float* __restrict__ xr, int K, int amode)
{
    int warp = blockIdx.x * (blockDim.x >> 5) + (threadIdx.x >> 5);
    int lane = threadIdx.x & 31;
    const float* row;
    if (amode) {
        int s = warp >> 7, b = warp & 127;
        row = A + ((size_t)b * Ss + s) * K;
    } else {
        row = A + (size_t)warp * K;
    }
    float az = 0.f, ar = 0.f;
    for (int k = lane; k < K; k += 32) {
        float v = row[k];
        az = fmaf(v, Wxz[k], az);
        ar = fmaf(v, Wxr[k], ar);
    }
#pragma unroll
    for (int d = 16; d; d >>= 1) {
        az += __shfl_down_sync(0xffffffffu, az, d);
        ar += __shfl_down_sync(0xffffffffu, ar, d);
    }
    if (lane == 0) { xz[warp] = az; xr[warp] = ar + bxr[0]; }
}

// ------------------------- SGEMM (f32x2): C[r,n] = sum_k Arow(r)[k]*Bw[n,k] ----
// 128x128 tile, K-step 8, 256 threads, 8x8 microtile via 8x(4 f32x2 pairs).
// EPI==0: C row-major. EPI==1: sigmoid(v + bias[n]) scattered to (B,S,N).
template <int EPI>
__global__ void __launch_bounds__(256) sgemm_nt(
    const float* __restrict__ A, const float* __restrict__ Bw,
    float* __restrict__ C, int N, int K, int amode,
    const float* __restrict__ bias)
{
    __shared__ float sA[8][132];   // row stride 528B = 33*16 -> 16B aligned rows
    __shared__ float sB[8][132];

    const int tid = threadIdx.x;
    const int m0 = blockIdx.x * 128;
    const int n0 = blockIdx.y * 128;
    const int tx = tid & 15, ty = tid >> 4;
    const int lr = tid >> 1;
    const int lq = (tid & 1) * 4;

    const float* aptr;
    {
        int arow = m0 + lr;
        if (amode) {
            int s = arow >> 7, b = arow & 127;
            aptr = A + ((size_t)b * Ss + s) * K;
        } else {
            aptr = A + (size_t)arow * K;
        }
    }
    const float* bptr = Bw + (size_t)(n0 + lr) * K;

    unsigned long long acc2[8][4];
#pragma unroll
    for (int i = 0; i < 8; i++)
#pragma unroll
        for (int j = 0; j < 4; j++) acc2[i][j] = 0ull;

    float4 av = *(const float4*)(aptr + lq);
    float4 bv = *(const float4*)(bptr + lq);

#pragma unroll 1
    for (int k0 = 0; k0 < K; k0 += 8) {
        __syncthreads();
        sA[lq + 0][lr] = av.x; sA[lq + 1][lr] = av.y;
        sA[lq + 2][lr] = av.z; sA[lq + 3][lr] = av.w;
        sB[lq + 0][lr] = bv.x; sB[lq + 1][lr] = bv.y;
        sB[lq + 2][lr] = bv.z; sB[lq + 3][lr] = bv.w;
        __syncthreads();
        if (k0 + 8 < K) {           // prefetch next slab behind compute
            av = *(const float4*)(aptr + k0 + 8 + lq);
            bv = *(const float4*)(bptr + k0 + 8 + lq);
        }
#pragma unroll
        for (int k = 0; k < 8; k++) {
            const float4* sa4 = (const float4*)(&sA[k][0]);
            const ulonglong2* sb2 = (const ulonglong2*)(&sB[k][0]);
            float4 a0 = sa4[ty], a1 = sa4[16 + ty];
            ulonglong2 b0 = sb2[tx], b1 = sb2[16 + tx];
            unsigned long long ap[8];
            ap[0] = pack2(a0.x, a0.x); ap[1] = pack2(a0.y, a0.y);
            ap[2] = pack2(a0.z, a0.z); ap[3] = pack2(a0.w, a0.w);
            ap[4] = pack2(a1.x, a1.x); ap[5] = pack2(a1.y, a1.y);
            ap[6] = pack2(a1.z, a1.z); ap[7] = pack2(a1.w, a1.w);
#pragma unroll
            for (int i = 0; i < 8; i++) {
                acc2[i][0] = ffma2(ap[i], b0.x, acc2[i][0]);
                acc2[i][1] = ffma2(ap[i], b0.y, acc2[i][1]);
                acc2[i][2] = ffma2(ap[i], b1.x, acc2[i][2]);
                acc2[i][3] = ffma2(ap[i], b1.y, acc2[i][3]);
            }
        }
    }

#pragma unroll
    for (int ai = 0; ai < 8; ai++) {
        int row = m0 + ((ai >> 2) * 64) + ty * 4 + (ai & 3);
#pragma unroll
        for (int half = 0; half < 2; half++) {
            int col = n0 + half * 64 + tx * 4;
            float2 p0 = unpack2(acc2[ai][half * 2 + 0]);
            float2 p1 = unpack2(acc2[ai][half * 2 + 1]);
            float4 v = make_float4(p0.x, p0.y, p1.x, p1.y);
            if (EPI == 0) {
                *(float4*)&C[(size_t)row * N + col] = v;
            } else {
                int s = row >> 7, b = row & 127;
                float4 bs = *(const float4*)(bias + col);
                v.x = 1.f / (1.f + expf(-(v.x + bs.x)));
                v.y = 1.f / (1.f + expf(-(v.y + bs.y)));
                v.z = 1.f / (1.f + expf(-(v.z + bs.z)));
                v.w = 1.f / (1.f + expf(-(v.w + bs.w)));
                *(float4*)&C[((size_t)b * Ss + s) * N + col] = v;
            }
        }
    }
}

// ------------------------- persistent GRU scan (one launch per layer) ----------
#define SCAN_SMEM_FLOATS (32*Hh + Hh + Hh + 8*1152 + 256 + 256 + 32 + 32 + 32)
#define SCAN_SMEM_BYTES  (SCAN_SMEM_FLOATS * 4)

__global__ void __launch_bounds__(256) gru_scan(
    const float* __restrict__ xz, const float* __restrict__ xr,
    const float* __restrict__ xg,
    const float* __restrict__ Whz, const float* __restrict__ Whr,
    const float* __restrict__ Whg,
    const float* __restrict__ bhz, const float* __restrict__ bhg,
    const float* __restrict__ h0l,
    float* __restrict__ hs, float* __restrict__ hTl)
{
    extern __shared__ float smem[];
    float* Wg   = smem;                  // [32][1024]
    float* swz  = Wg + 32 * Hh;          // [1024]
    float* swr  = swz + Hh;              // [1024]
    float* red  = swr + Hh;              // [8][32][36]
    float* zred = red + 8 * 1152;        // [8][32]
    float* rred = zred + 256;            // [8][32]
    float* zv   = rred + 256;            // [32]
    float* rv   = zv + 32;               // [32]
    float* bg   = rv + 32;               // [32]

    const int tid  = threadIdx.x;
    const int w    = tid >> 5, lane = tid & 31;
    const int bt   = blockIdx.x >> 5, nt = blockIdx.x & 31;
    const int b0   = bt * 32, j0 = nt * 32;

    for (int idx = tid; idx < 32 * Hh; idx += 256)
        Wg[idx] = Whg[(size_t)(j0 + (idx >> 10)) * Hh + (idx & 1023)];
    for (int idx = tid; idx < Hh; idx += 256) { swz[idx] = Whz[idx]; swr[idx] = Whr[idx]; }
    if (tid < 32) bg[tid] = bhg[j0 + tid];
    const float bz = bhz[0];

    for (int idx = blockIdx.x * 256 + tid; idx < Bb * Hh; idx += NBLK * 256) {
        int b = idx & 127, k = idx >> 7;
        g_ht[0][idx] = h0l[(size_t)b * (2 * Hh) + k];
    }
    grid_barrier();

    const int ju = tid >> 3;
    const int bq = (tid & 7) * 4;
    const int kbase = w * 128;
    const ulonglong2* Wg2 = (const ulonglong2*)Wg;
    const ulonglong2* z2  = (const ulonglong2*)swz;
    const ulonglong2* r2  = (const ulonglong2*)swr;
    int cur = 0;

#pragma unroll 1
    for (int s = 0; s < Ss; s++) {
        const float* ht_c = g_ht[cur];
        float* ht_n = g_ht[cur ^ 1];

        float4 ho = __ldcg((const float4*)(ht_c + (j0 + ju) * Bb + b0 + bq));
        float xgv[4];
#pragma unroll
        for (int i = 0; i < 4; i++)
            xgv[i] = xg[(size_t)(s * Bb + b0 + bq + i) * Hh + j0 + ju];

        // --- matvec partial: lane owns b=b0+lane, warp owns k in [kbase,kbase+128)
        unsigned long long accP[32];
#pragma unroll
        for (int j = 0; j < 32; j++) accP[j] = 0ull;
        unsigned long long zaccP = 0ull, raccP = 0ull;

        float h0v = __ldcg(ht_c + (kbase + 0) * Bb + b0 + lane);
        float h1v = __ldcg(ht_c + (kbase + 1) * Bb + b0 + lane);
        float h2v = __ldcg(ht_c + (kbase + 2) * Bb + b0 + lane);
        float h3v = __ldcg(ht_c + (kbase + 3) * Bb + b0 + lane);

#pragma unroll 4
        for (int q = 0; q < 32; q++) {
            unsigned long long a01 = pack2(h0v, h1v);
            unsigned long long a23 = pack2(h2v, h3v);
            if (q < 31) {
                int kn = kbase + (q + 1) * 4;
                h0v = __ldcg(ht_c + (kn + 0) * Bb + b0 + lane);
                h1v = __ldcg(ht_c + (kn + 1) * Bb + b0 + lane);
                h2v = __ldcg(ht_c + (kn + 2) * Bb + b0 + lane);
                h3v = __ldcg(ht_c + (kn + 3) * Bb + b0 + lane);
            }
            int kq = (kbase >> 2) + q;
            ulonglong2 zq = z2[kq];
            ulonglong2 rq = r2[kq];
            zaccP = ffma2(a01, zq.x, ffma2(a23, zq.y, zaccP));
            raccP = ffma2(a01, rq.x, ffma2(a23, rq.y, raccP));
#pragma unroll
            for (int j = 0; j < 32; j++) {
                ulonglong2 wq = Wg2[j * 256 + kq];
                accP[j] = ffma2(a01, wq.x, ffma2(a23, wq.y, accP[j]));
            }
        }

        // --- cross-warp reduction
        {
            float2 zp = unpack2(zaccP), rp = unpack2(raccP);
            zred[w * 32 + lane] = zp.x + zp.y;
            rred[w * 32 + lane] = rp.x + rp.y;
            float* rw = red + w * 1152;
#pragma unroll
            for (int j = 0; j < 32; j++) {
                float2 p = unpack2(accP[j]);
                rw[j * 36 + lane] = p.x + p.y;
            }
        }
        __syncthreads();
        if (tid < 32) {
            float zs = 0.f, rs = 0.f;
#pragma unroll
            for (int ww = 0; ww < 8; ww++) { zs += zred[ww * 32 + tid]; rs += rred[ww * 32 + tid]; }
            float zval = xz[s * Bb + b0 + tid] + zs + bz;
            float rval = xr[s * Bb + b0 + tid] + rs;
            zv[tid] = 1.f / (1.f + expf(-zval));
            rv[tid] = 1.f / (1.f + expf(-rval));
        }
        __syncthreads();

        float m0 = 0.f, m1 = 0.f, m2 = 0.f, m3 = 0.f;
#pragma unroll
        for (int ww = 0; ww < 8; ww++) {
            float4 p = *(const float4*)(red + ww * 1152 + ju * 36 + bq);
            m0 += p.x; m1 += p.y; m2 += p.z; m3 += p.w;
        }
        float mm[4] = {m0, m1, m2, m3};
        float hof[4] = {ho.x, ho.y, ho.z, ho.w};
        float hn[4];
#pragma unroll
        for (int i = 0; i < 4; i++) {
            int bb = b0 + bq + i;
            float g = tanhf(xgv[i] + rv[bq + i] * mm[i] + bg[ju]);
            float zz = zv[bq + i];
            float v = zz * hof[i] + (1.f - zz) * g;
            hn[i] = v;
            hs[(size_t)(s * Bb + bb) * Hh + j0 + ju] = v;
        }
        __stcg((float4*)(ht_n + (j0 + ju) * Bb + b0 + bq),
               make_float4(hn[0], hn[1], hn[2], hn[3]));
        cur ^= 1;
        grid_barrier();
    }

    const float* ht_c = g_ht[cur];
#pragma unroll
    for (int i = 0; i < 4; i++)
        hTl[(size_t)(b0 + bq + i) * (2 * Hh) + j0 + ju] =
            __ldcg(ht_c + (j0 + ju) * Bb + b0 + bq + i);
}

// ------------------------- launcher -------------------------------------------
extern "C" void kernel_launch(void* const* d_in, const int* in_sizes, int n_in,
                              void* d_out, int out_size) {
    (void)in_sizes; (void)n_in; (void)out_size;

    const float* x    = (const float*)d_in[0];
    const float* h0   = (const float*)d_in[1];
    const float* Wxz0 = (const float*)d_in[2];
    const float* Whz0 = (const float*)d_in[3];
    const float* bhz0 = (const float*)d_in[4];
    const float* Wxr0 = (const float*)d_in[5];
    const float* bxr0 = (const float*)d_in[6];
    const float* Whr0 = (const float*)d_in[7];
    const float* Wxg0 = (const float*)d_in[8];
    const float* Whg0 = (const float*)d_in[9];
    const float* bhg0 = (const float*)d_in[10];
    const float* Wxz1 = (const float*)d_in[11];
    const float* Whz1 = (const float*)d_in[12];
    const float* bhz1 = (const float*)d_in[13];
    const float* Wxr1 = (const float*)d_in[14];
    const float* bxr1 = (const float*)d_in[15];
    const float* Whr1 = (const float*)d_in[16];
    const float* Wxg1 = (const float*)d_in[17];
    const float* Whg1 = (const float*)d_in[18];
    const float* bhg1 = (const float*)d_in[19];
    const float* Why  = (const float*)d_in[20];
    const float* bhy  = (const float*)d_in[21];

    float* out   = (float*)d_out;
    float* out_y = out;                                  // (B,S,O)
    float* out_h = out + (size_t)Bb * Ss * Oo;           // (B,2,H)

    float *xzp, *xrp, *xgp, *hsp;
    cudaGetSymbolAddress((void**)&xzp, g_xz);
    cudaGetSymbolAddress((void**)&xrp, g_xr);
    cudaGetSymbolAddress((void**)&xgp, g_xg);
    cudaGetSymbolAddress((void**)&hsp, g_hs);

    cudaFuncSetAttribute(gru_scan, cudaFuncAttributeMaxDynamicSharedMemorySize,
                         SCAN_SMEM_BYTES);

    const int M = Ss * Bb;                // 32768
    dim3 gemmBlk(256);
    dim3 gemmGridH(M / 128, Hh / 128);    // (256, 8)
    dim3 gemmGridO(M / 128, Oo / 128);    // (256, 2)
    int projBlocks = M / 8;

    // ----- layer 0 -----
    proj_zr<<<projBlocks, 256>>>(x, Wxz0, Wxr0, bxr0, xzp, xrp, Ii, 1);
    sgemm_nt<0><<<gemmGridH, gemmBlk>>>(x, Wxg0, xgp, Hh, Ii, 1, nullptr);
    gru_scan<<<NBLK, 256, SCAN_SMEM_BYTES>>>(
        xzp, xrp, xgp, Whz0, Whr0, Whg0, bhz0, bhg0,
        h0 + 0 * Hh, hsp, out_h + 0 * Hh);

    // ----- layer 1 -----
    proj_zr<<<projBlocks, 256>>>(hsp, Wxz1, Wxr1, bxr1, xzp, xrp, Hh, 0);
    sgemm_nt<0><<<gemmGridH, gemmBlk>>>(hsp, Wxg1, xgp, Hh, Hh, 0, nullptr);
    gru_scan<<<NBLK, 256, SCAN_SMEM_BYTES>>>(
        xzp, xrp, xgp, Whz1, Whr1, Whg1, bhz1, bhg1,
        h0 + 1 * Hh, hsp, out_h + 1 * Hh);

    // ----- output head: sigmoid(hs1 @ Why^T + bhy) -> (B,S,O) -----
    sgemm_nt<1><<<gemmGridO, gemmBlk>>>(hsp, Why, out_y, Oo, Hh, 0, bhy);
}

// round 9
// speedup vs baseline: 1.3511x; 1.3511x over previous
#include <cuda_runtime.h>
#include <mma.h>
#include <math.h>
#include <stdint.h>
#include <stddef.h>

using namespace nvcuda;

#define Bb 128
#define Ss 256
#define Ii 256
#define Hh 1024
#define Oo 256
#define NBLK 128

// ------------------------- device scratch (no allocations allowed) -------------
__device__ float g_xz[Ss * Bb];
__device__ float g_xr[Ss * Bb];
__device__ float g_xg[(size_t)Ss * Bb * Hh];   // 128 MB
__device__ float g_hs[(size_t)Ss * Bb * Hh];   // 128 MB
__device__ float g_ht[2][Hh * Bb];             // hidden state, k-major [k][b], dbl buf
__device__ unsigned g_bar_count;
__device__ volatile unsigned g_bar_gen;

// ------------------------- grid barrier (all NBLK CTAs resident) ---------------
__device__ __forceinline__ void grid_barrier() {
    __syncthreads();
    if (threadIdx.x == 0) {
        __threadfence();
        unsigned gen = g_bar_gen;
        unsigned t = atomicAdd(&g_bar_count, 1u);
        if (t == gridDim.x - 1) {
            g_bar_count = 0;
            __threadfence();
            g_bar_gen = gen + 1u;
        } else {
            while (g_bar_gen == gen) { __nanosleep(32); }
        }
        __threadfence();
    }
    __syncthreads();
}

// ------------------------- scalar-gate projections ----------------------------
__global__ void __launch_bounds__(256) proj_zr(
    const float* __restrict__ A, const float* __restrict__ Wxz,
    const float* __restrict__ Wxr, const float* __restrict__ bxr,
    float* __restrict__ xz, float* __restrict__ xr, int K, int amode)
{
    int warp = blockIdx.x * (blockDim.x >> 5) + (threadIdx.x >> 5);
    int lane = threadIdx.x & 31;
    const float* row;
    if (amode) {
        int s = warp >> 7, b = warp & 127;
        row = A + ((size_t)b * Ss + s) * K;
    } else {
        row = A + (size_t)warp * K;
    }
    float az = 0.f, ar = 0.f;
    for (int k = lane; k < K; k += 32) {
        float v = row[k];
        az = fmaf(v, Wxz[k], az);
        ar = fmaf(v, Wxr[k], ar);
    }
#pragma unroll
    for (int d = 16; d; d >>= 1) {
        az += __shfl_down_sync(0xffffffffu, az, d);
        ar += __shfl_down_sync(0xffffffffu, ar, d);
    }
    if (lane == 0) { xz[warp] = az; xr[warp] = ar + bxr[0]; }
}

// ------------------------- tf32 WMMA GEMM: C[r,n] = sum_k Arow(r)[k]*Bw[n,k] ---
// 128x128 tile, kstep 16, 256 threads. 8 warps: warp (wr,wc) computes 32x64 via
// 2x4 wmma 16x16x8 frags. A row-major in smem, B (N-major,K-contig) is exactly
// col-major KxN so wmma col_major loads it directly.
// EPI==0: C row-major. EPI==1: sigmoid(v + bias[n]) scattered to (B,S,N).
template <int EPI>
__global__ void __launch_bounds__(256) wgemm_tf32(
    const float* __restrict__ A, const float* __restrict__ Bw,
    float* __restrict__ C, int N, int K, int amode,
    const float* __restrict__ bias)
{
    __shared__ float sA[128][20];   // [m][k], ld=20 (mult of 4 for wmma)
    __shared__ float sB[128][20];   // [n][k], ld=20

    const int tid = threadIdx.x;
    const int m0 = blockIdx.x * 128;
    const int n0 = blockIdx.y * 128;

    const int r0 = tid >> 2;          // 0..63
    const int r1 = r0 + 64;           // 64..127
    const int qc = (tid & 3) * 4;     // 0,4,8,12

    const float* aP0;
    const float* aP1;
    {
        int ar0 = m0 + r0, ar1 = m0 + r1;
        if (amode) {
            int s0 = ar0 >> 7, b0_ = ar0 & 127;
            int s1 = ar1 >> 7, b1_ = ar1 & 127;
            aP0 = A + ((size_t)b0_ * Ss + s0) * K;
            aP1 = A + ((size_t)b1_ * Ss + s1) * K;
        } else {
            aP0 = A + (size_t)ar0 * K;
            aP1 = A + (size_t)ar1 * K;
        }
    }
    const float* bP0 = Bw + (size_t)(n0 + r0) * K;
    const float* bP1 = Bw + (size_t)(n0 + r1) * K;

    const int w  = tid >> 5;
    const int wr = w >> 1;            // 0..3 -> m offset wr*32
    const int wc = w & 1;             // 0..1 -> n offset wc*64
    const int lane = tid & 31;

    wmma::fragment<wmma::accumulator, 16, 16, 8, float> cf[2][4];
#pragma unroll
    for (int i = 0; i < 2; i++)
#pragma unroll
        for (int j = 0; j < 4; j++) wmma::fill_fragment(cf[i][j], 0.0f);

    float4 a0 = *(const float4*)(aP0 + qc);
    float4 a1 = *(const float4*)(aP1 + qc);
    float4 b0 = *(const float4*)(bP0 + qc);
    float4 b1 = *(const float4*)(bP1 + qc);

#pragma unroll 1
    for (int k0 = 0; k0 < K; k0 += 16) {
        __syncthreads();
        *(float4*)&sA[r0][qc] = a0;
        *(float4*)&sA[r1][qc] = a1;
        *(float4*)&sB[r0][qc] = b0;
        *(float4*)&sB[r1][qc] = b1;
        __syncthreads();
        if (k0 + 16 < K) {            // prefetch next slab behind compute
            a0 = *(const float4*)(aP0 + k0 + 16 + qc);
            a1 = *(const float4*)(aP1 + k0 + 16 + qc);
            b0 = *(const float4*)(bP0 + k0 + 16 + qc);
            b1 = *(const float4*)(bP1 + k0 + 16 + qc);
        }
#pragma unroll
        for (int kk = 0; kk < 16; kk += 8) {
            wmma::fragment<wmma::matrix_a, 16, 16, 8, wmma::precision::tf32,
                           wmma::row_major> af[2];
            wmma::fragment<wmma::matrix_b, 16, 16, 8, wmma::precision::tf32,
                           wmma::col_major> bf[4];
#pragma unroll
            for (int i = 0; i < 2; i++) {
                wmma::load_matrix_sync(af[i], &sA[wr * 32 + i * 16][kk], 20);
#pragma unroll
                for (int t = 0; t < af[i].num_elements; t++)
                    af[i].x[t] = wmma::__float_to_tf32(af[i].x[t]);
            }
#pragma unroll
            for (int j = 0; j < 4; j++) {
                wmma::load_matrix_sync(bf[j], &sB[wc * 64 + j * 16][kk], 20);
#pragma unroll
                for (int t = 0; t < bf[j].num_elements; t++)
                    bf[j].x[t] = wmma::__float_to_tf32(bf[j].x[t]);
            }
#pragma unroll
            for (int i = 0; i < 2; i++)
#pragma unroll
                for (int j = 0; j < 4; j++)
                    wmma::mma_sync(cf[i][j], af[i], bf[j], cf[i][j]);
        }
    }

    if (EPI == 0) {
#pragma unroll
        for (int i = 0; i < 2; i++)
#pragma unroll
            for (int j = 0; j < 4; j++)
                wmma::store_matrix_sync(
                    &C[(size_t)(m0 + wr * 32 + i * 16) * N + n0 + wc * 64 + j * 16],
                    cf[i][j], N, wmma::mem_row_major);
    } else {
        // head: stage each frag in a per-warp smem patch, sigmoid+bias, scatter
        __syncthreads();
        float* patch = &sA[0][0] + w * 320;   // 16 rows x ld 20 per warp
        const int sIdx = m0 >> 7;             // s constant within the M-tile
#pragma unroll
        for (int i = 0; i < 2; i++)
#pragma unroll
            for (int j = 0; j < 4; j++) {
                wmma::store_matrix_sync(patch, cf[i][j], 20, wmma::mem_row_major);
                __syncwarp();
                int colb = n0 + wc * 64 + j * 16;
                int rowb = wr * 32 + i * 16;  // == b base (m0 multiple of 128)
#pragma unroll
                for (int e = 0; e < 8; e++) {
                    int idx = lane * 8 + e;
                    int pr = idx >> 4, pc = idx & 15;
                    int b = rowb + pr;
                    int col = colb + pc;
                    float v = patch[pr * 20 + pc] + bias[col];
                    v = 1.f / (1.f + expf(-v));
                    C[((size_t)b * Ss + sIdx) * N + col] = v;
                }
                __syncwarp();
            }
    }
}

// ------------------------- persistent GRU scan (one launch per layer) ----------
#define SCAN_SMEM_FLOATS (32*Hh + Hh + Hh + 8*1152 + 256 + 256 + 32 + 32 + 32)
#define SCAN_SMEM_BYTES  (SCAN_SMEM_FLOATS * 4)

__global__ void __launch_bounds__(256) gru_scan(
    const float* __restrict__ xz, const float* __restrict__ xr,
    const float* __restrict__ xg,
    const float* __restrict__ Whz, const float* __restrict__ Whr,
    const float* __restrict__ Whg,
    const float* __restrict__ bhz, const float* __restrict__ bhg,
    const float* __restrict__ h0l,
    float* __restrict__ hs, float* __restrict__ hTl)
{
    extern __shared__ float smem[];
    float* Wg   = smem;                  // [32][1024]
    float* swz  = Wg + 32 * Hh;          // [1024]
    float* swr  = swz + Hh;              // [1024]
    float* red  = swr + Hh;              // [8][32][36]
    float* zred = red + 8 * 1152;        // [8][32]
    float* rred = zred + 256;            // [8][32]
    float* zv   = rred + 256;            // [32]
    float* rv   = zv + 32;               // [32]
    float* bg   = rv + 32;               // [32]

    const int tid  = threadIdx.x;
    const int w    = tid >> 5, lane = tid & 31;
    const int bt   = blockIdx.x >> 5, nt = blockIdx.x & 31;
    const int b0   = bt * 32, j0 = nt * 32;

    for (int idx = tid; idx < 32 * Hh; idx += 256)
        Wg[idx] = Whg[(size_t)(j0 + (idx >> 10)) * Hh + (idx & 1023)];
    for (int idx = tid; idx < Hh; idx += 256) { swz[idx] = Whz[idx]; swr[idx] = Whr[idx]; }
    if (tid < 32) bg[tid] = bhg[j0 + tid];
    const float bz = bhz[0];

    for (int idx = blockIdx.x * 256 + tid; idx < Bb * Hh; idx += NBLK * 256) {
        int b = idx & 127, k = idx >> 7;
        g_ht[0][idx] = h0l[(size_t)b * (2 * Hh) + k];
    }
    grid_barrier();

    const int ju = tid >> 3;
    const int bq = (tid & 7) * 4;
    const int kbase = w * 128;
    const float4* Wg4 = (const float4*)Wg;
    int cur = 0;

#pragma unroll 1
    for (int s = 0; s < Ss; s++) {
        const float* ht_c = g_ht[cur];
        float* ht_n = g_ht[cur ^ 1];

        float4 ho = __ldcg((const float4*)(ht_c + (j0 + ju) * Bb + b0 + bq));
        float xgv[4];
#pragma unroll
        for (int i = 0; i < 4; i++)
            xgv[i] = xg[(size_t)(s * Bb + b0 + bq + i) * Hh + j0 + ju];

        // --- matvec partial: lane owns b=b0+lane, warp owns k in [kbase,kbase+128)
        float acc[32];
#pragma unroll
        for (int j = 0; j < 32; j++) acc[j] = 0.f;
        float zacc = 0.f, racc = 0.f;

        float h0v = __ldcg(ht_c + (kbase + 0) * Bb + b0 + lane);
        float h1v = __ldcg(ht_c + (kbase + 1) * Bb + b0 + lane);
        float h2v = __ldcg(ht_c + (kbase + 2) * Bb + b0 + lane);
        float h3v = __ldcg(ht_c + (kbase + 3) * Bb + b0 + lane);

#pragma unroll 4
        for (int q = 0; q < 32; q++) {
            float a0 = h0v, a1 = h1v, a2 = h2v, a3 = h3v;
            if (q < 31) {
                int kn = kbase + (q + 1) * 4;
                h0v = __ldcg(ht_c + (kn + 0) * Bb + b0 + lane);
                h1v = __ldcg(ht_c + (kn + 1) * Bb + b0 + lane);
                h2v = __ldcg(ht_c + (kn + 2) * Bb + b0 + lane);
                h3v = __ldcg(ht_c + (kn + 3) * Bb + b0 + lane);
            }
            int kq = (kbase >> 2) + q;
            float4 zq = ((const float4*)swz)[kq];
            float4 rq = ((const float4*)swr)[kq];
            zacc = fmaf(a0, zq.x, fmaf(a1, zq.y, fmaf(a2, zq.z, fmaf(a3, zq.w, zacc))));
            racc = fmaf(a0, rq.x, fmaf(a1, rq.y, fmaf(a2, rq.z, fmaf(a3, rq.w, racc))));
#pragma unroll
            for (int j = 0; j < 32; j++) {
                float4 wq = Wg4[j * 256 + kq];
                acc[j] = fmaf(a0, wq.x, fmaf(a1, wq.y, fmaf(a2, wq.z, fmaf(a3, wq.w, acc[j]))));
            }
        }

        // --- cross-warp reduction
        zred[w * 32 + lane] = zacc;
        rred[w * 32 + lane] = racc;
        {
            float* rw = red + w * 1152;
#pragma unroll
            for (int j = 0; j < 32; j++) rw[j * 36 + lane] = acc[j];
        }
        __syncthreads();
        if (tid < 32) {
            float zs = 0.f, rs = 0.f;
#pragma unroll
            for (int ww = 0; ww < 8; ww++) { zs += zred[ww * 32 + tid]; rs += rred[ww * 32 + tid]; }
            float zval = xz[s * Bb + b0 + tid] + zs + bz;
            float rval = xr[s * Bb + b0 + tid] + rs;
            zv[tid] = 1.f / (1.f + expf(-zval));
            rv[tid] = 1.f / (1.f + expf(-rval));
        }
        __syncthreads();

        float m0 = 0.f, m1 = 0.f, m2 = 0.f, m3 = 0.f;
#pragma unroll
        for (int ww = 0; ww < 8; ww++) {
            float4 p = *(const float4*)(red + ww * 1152 + ju * 36 + bq);
            m0 += p.x; m1 += p.y; m2 += p.z; m3 += p.w;
        }
        float mm[4] = {m0, m1, m2, m3};
        float hof[4] = {ho.x, ho.y, ho.z, ho.w};
        float hn[4];
#pragma unroll
        for (int i = 0; i < 4; i++) {
            int bb = b0 + bq + i;
            float g = tanhf(xgv[i] + rv[bq + i] * mm[i] + bg[ju]);
            float zz = zv[bq + i];
            float v = zz * hof[i] + (1.f - zz) * g;
            hn[i] = v;
            hs[(size_t)(s * Bb + bb) * Hh + j0 + ju] = v;
        }
        __stcg((float4*)(ht_n + (j0 + ju) * Bb + b0 + bq),
               make_float4(hn[0], hn[1], hn[2], hn[3]));
        cur ^= 1;
        grid_barrier();
    }

    const float* ht_c = g_ht[cur];
#pragma unroll
    for (int i = 0; i < 4; i++)
        hTl[(size_t)(b0 + bq + i) * (2 * Hh) + j0 + ju] =
            __ldcg(ht_c + (j0 + ju) * Bb + b0 + bq + i);
}

// ------------------------- launcher -------------------------------------------
extern "C" void kernel_launch(void* const* d_in, const int* in_sizes, int n_in,
                              void* d_out, int out_size) {
    (void)in_sizes; (void)n_in; (void)out_size;

    const float* x    = (const float*)d_in[0];
    const float* h0   = (const float*)d_in[1];
    const float* Wxz0 = (const float*)d_in[2];
    const float* Whz0 = (const float*)d_in[3];
    const float* bhz0 = (const float*)d_in[4];
    const float* Wxr0 = (const float*)d_in[5];
    const float* bxr0 = (const float*)d_in[6];
    const float* Whr0 = (const float*)d_in[7];
    const float* Wxg0 = (const float*)d_in[8];
    const float* Whg0 = (const float*)d_in[9];
    const float* bhg0 = (const float*)d_in[10];
    const float* Wxz1 = (const float*)d_in[11];
    const float* Whz1 = (const float*)d_in[12];
    const float* bhz1 = (const float*)d_in[13];
    const float* Wxr1 = (const float*)d_in[14];
    const float* bxr1 = (const float*)d_in[15];
    const float* Whr1 = (const float*)d_in[16];
    const float* Wxg1 = (const float*)d_in[17];
    const float* Whg1 = (const float*)d_in[18];
    const float* bhg1 = (const float*)d_in[19];
    const float* Why  = (const float*)d_in[20];
    const float* bhy  = (const float*)d_in[21];

    float* out   = (float*)d_out;
    float* out_y = out;                                  // (B,S,O)
    float* out_h = out + (size_t)Bb * Ss * Oo;           // (B,2,H)

    float *xzp, *xrp, *xgp, *hsp;
    cudaGetSymbolAddress((void**)&xzp, g_xz);
    cudaGetSymbolAddress((void**)&xrp, g_xr);
    cudaGetSymbolAddress((void**)&xgp, g_xg);
    cudaGetSymbolAddress((void**)&hsp, g_hs);

    cudaFuncSetAttribute(gru_scan, cudaFuncAttributeMaxDynamicSharedMemorySize,
                         SCAN_SMEM_BYTES);

    const int M = Ss * Bb;                // 32768
    dim3 gemmBlk(256);
    dim3 gemmGridH(M / 128, Hh / 128);    // (256, 8)
    dim3 gemmGridO(M / 128, Oo / 128);    // (256, 2)
    int projBlocks = M / 8;

    // ----- layer 0 -----
    proj_zr<<<projBlocks, 256>>>(x, Wxz0, Wxr0, bxr0, xzp, xrp, Ii, 1);
    wgemm_tf32<0><<<gemmGridH, gemmBlk>>>(x, Wxg0, xgp, Hh, Ii, 1, nullptr);
    gru_scan<<<NBLK, 256, SCAN_SMEM_BYTES>>>(
        xzp, xrp, xgp, Whz0, Whr0, Whg0, bhz0, bhg0,
        h0 + 0 * Hh, hsp, out_h + 0 * Hh);

    // ----- layer 1 -----
    proj_zr<<<projBlocks, 256>>>(hsp, Wxz1, Wxr1, bxr1, xzp, xrp, Hh, 0);
    wgemm_tf32<0><<<gemmGridH, gemmBlk>>>(hsp, Wxg1, xgp, Hh, Hh, 0, nullptr);
    gru_scan<<<NBLK, 256, SCAN_SMEM_BYTES>>>(
        xzp, xrp, xgp, Whz1, Whr1, Whg1, bhz1, bhg1,
        h0 + 1 * Hh, hsp, out_h + 1 * Hh);

    // ----- output head: sigmoid(hs1 @ Why^T + bhy) -> (B,S,O) -----
    wgemm_tf32<1><<<gemmGridO, gemmBlk>>>(hsp, Why, out_y, Oo, Hh, 0, bhy);
}

// round 10
// speedup vs baseline: 1.5779x; 1.1679x over previous
#include <cuda_runtime.h>
#include <mma.h>
#include <math.h>
#include <stdint.h>
#include <stddef.h>

using namespace nvcuda;

#define Bb 128
#define Ss 256
#define Ii 256
#define Hh 1024
#define Oo 256
#define NBLK 128

// ------------------------- device scratch (no allocations allowed) -------------
__device__ float g_xz[Ss * Bb];
__device__ float g_xr[Ss * Bb];
__device__ float g_xg[(size_t)Ss * Bb * Hh];   // 128 MB
__device__ float g_hs[(size_t)Ss * Bb * Hh];   // 128 MB
__device__ float g_ht[2][Hh * Bb];             // hidden state, k-major [k][b], dbl buf
__device__ unsigned g_bar_count;
__device__ volatile unsigned g_bar_gen;

// ------------------------- grid barrier (all NBLK CTAs resident) ---------------
__device__ __forceinline__ void grid_barrier() {
    __syncthreads();
    if (threadIdx.x == 0) {
        __threadfence();
        unsigned gen = g_bar_gen;
        unsigned t = atomicAdd(&g_bar_count, 1u);
        if (t == gridDim.x - 1) {
            g_bar_count = 0;
            __threadfence();
            g_bar_gen = gen + 1u;
        } else {
            while (g_bar_gen == gen) { __nanosleep(32); }
        }
        __threadfence();
    }
    __syncthreads();
}

// ------------------------- scalar-gate projections ----------------------------
__global__ void __launch_bounds__(256) proj_zr(
    const float* __restrict__ A, const float* __restrict__ Wxz,
    const float* __restrict__ Wxr, const float* __restrict__ bxr,
    float* __restrict__ xz, float* __restrict__ xr, int K, int amode)
{
    int warp = blockIdx.x * (blockDim.x >> 5) + (threadIdx.x >> 5);
    int lane = threadIdx.x & 31;
    const float* row;
    if (amode) {
        int s = warp >> 7, b = warp & 127;
        row = A + ((size_t)b * Ss + s) * K;
    } else {
        row = A + (size_t)warp * K;
    }
    float az = 0.f, ar = 0.f;
    for (int k = lane; k < K; k += 32) {
        float v = row[k];
        az = fmaf(v, Wxz[k], az);
        ar = fmaf(v, Wxr[k], ar);
    }
#pragma unroll
    for (int d = 16; d; d >>= 1) {
        az += __shfl_down_sync(0xffffffffu, az, d);
        ar += __shfl_down_sync(0xffffffffu, ar, d);
    }
    if (lane == 0) { xz[warp] = az; xr[warp] = ar + bxr[0]; }
}

// ------------------------- tf32 WMMA GEMM v2 -----------------------------------
// C[r,n] = sum_k Arow(r)[k] * Bw[n,k]. 128x128 tile, kstep 32, double-buffered
// smem (1 __syncthreads per stage), tf32 conversion at smem-store time, ld=36
// (conflict-free for wmma tf32 fragment loads). 8 warps: warp (wr,wc) owns 32x64.
// EPI==0: C row-major. EPI==1: sigmoid(v + bias[n]) scattered to (B,S,N).
#define GLD 36
#define GSTG (128 * GLD * 2)            // floats per stage (A block + B block)
#define WG_SMEM_BYTES (2 * GSTG * 4)    // 73728 B

template <int EPI>
__global__ void __launch_bounds__(256) wgemm_tf32(
    const float* __restrict__ A, const float* __restrict__ Bw,
    float* __restrict__ C, int N, int K, int amode,
    const float* __restrict__ bias)
{
    extern __shared__ float sm[];

    const int tid = threadIdx.x;
    const int m0 = blockIdx.x * 128;
    const int n0 = blockIdx.y * 128;

    // global staging: thread loads rows lrow+{0,32,64,96}, float4 at col lc4
    const int lrow = tid >> 3;
    const int lc4  = (tid & 7) * 4;

    const float* aP[4];
    const float* bP[4];
#pragma unroll
    for (int i = 0; i < 4; i++) {
        int r  = lrow + 32 * i;
        int ar = m0 + r;
        if (amode) {
            int s = ar >> 7, b = ar & 127;
            aP[i] = A + ((size_t)b * Ss + s) * K;
        } else {
            aP[i] = A + (size_t)ar * K;
        }
        bP[i] = Bw + (size_t)(n0 + r) * K;
    }

    const int w    = tid >> 5;
    const int wr   = w >> 1;   // m offset wr*32
    const int wc   = w & 1;    // n offset wc*64
    const int lane = tid & 31;

    wmma::fragment<wmma::accumulator, 16, 16, 8, float> cf[2][4];
#pragma unroll
    for (int i = 0; i < 2; i++)
#pragma unroll
        for (int j = 0; j < 4; j++) wmma::fill_fragment(cf[i][j], 0.0f);

    float4 av[4], bv[4];
#pragma unroll
    for (int i = 0; i < 4; i++) {
        av[i] = *(const float4*)(aP[i] + lc4);
        bv[i] = *(const float4*)(bP[i] + lc4);
    }

    int cur = 0;
#pragma unroll 1
    for (int k0 = 0; k0 < K; k0 += 32) {
        float* sa = sm + cur * GSTG;
        float* sb = sa + 128 * GLD;
        // store prefetched slab, converting to tf32 bits once
#pragma unroll
        for (int i = 0; i < 4; i++) {
            int row = lrow + 32 * i;
            float* pa = sa + row * GLD + lc4;
            pa[0] = wmma::__float_to_tf32(av[i].x);
            pa[1] = wmma::__float_to_tf32(av[i].y);
            pa[2] = wmma::__float_to_tf32(av[i].z);
            pa[3] = wmma::__float_to_tf32(av[i].w);
            float* pb = sb + row * GLD + lc4;
            pb[0] = wmma::__float_to_tf32(bv[i].x);
            pb[1] = wmma::__float_to_tf32(bv[i].y);
            pb[2] = wmma::__float_to_tf32(bv[i].z);
            pb[3] = wmma::__float_to_tf32(bv[i].w);
        }
        __syncthreads();
        if (k0 + 32 < K) {   // prefetch next slab behind this stage's compute
#pragma unroll
            for (int i = 0; i < 4; i++) {
                av[i] = *(const float4*)(aP[i] + k0 + 32 + lc4);
                bv[i] = *(const float4*)(bP[i] + k0 + 32 + lc4);
            }
        }
        const float* sa_r = sa + (wr * 32) * GLD;
        const float* sb_r = sb + (wc * 64) * GLD;
#pragma unroll
        for (int kk = 0; kk < 32; kk += 8) {
            wmma::fragment<wmma::matrix_a, 16, 16, 8, wmma::precision::tf32,
                           wmma::row_major> af[2];
            wmma::fragment<wmma::matrix_b, 16, 16, 8, wmma::precision::tf32,
                           wmma::col_major> bf[4];
            wmma::load_matrix_sync(af[0], sa_r + kk, GLD);
            wmma::load_matrix_sync(af[1], sa_r + 16 * GLD + kk, GLD);
#pragma unroll
            for (int j = 0; j < 4; j++)
                wmma::load_matrix_sync(bf[j], sb_r + j * 16 * GLD + kk, GLD);
#pragma unroll
            for (int i = 0; i < 2; i++)
#pragma unroll
                for (int j = 0; j < 4; j++)
                    wmma::mma_sync(cf[i][j], af[i], bf[j], cf[i][j]);
        }
        cur ^= 1;
    }

    if (EPI == 0) {
#pragma unroll
        for (int i = 0; i < 2; i++)
#pragma unroll
            for (int j = 0; j < 4; j++)
                wmma::store_matrix_sync(
                    &C[(size_t)(m0 + wr * 32 + i * 16) * N + n0 + wc * 64 + j * 16],
                    cf[i][j], N, wmma::mem_row_major);
    } else {
        // head: per-warp smem patch, sigmoid+bias, scatter to (B,S,N)
        __syncthreads();
        float* patch = sm + w * 320;          // 16 rows x ld 20
        const int sIdx = m0 >> 7;             // s constant within the M-tile
#pragma unroll
        for (int i = 0; i < 2; i++)
#pragma unroll
            for (int j = 0; j < 4; j++) {
                wmma::store_matrix_sync(patch, cf[i][j], 20, wmma::mem_row_major);
                __syncwarp();
                int colb = n0 + wc * 64 + j * 16;
                int rowb = wr * 32 + i * 16;  // == b base
#pragma unroll
                for (int e = 0; e < 8; e++) {
                    int idx = lane * 8 + e;
                    int pr = idx >> 4, pc = idx & 15;
                    int b = rowb + pr;
                    int col = colb + pc;
                    float v = patch[pr * 20 + pc] + bias[col];
                    v = 1.f / (1.f + expf(-v));
                    C[((size_t)b * Ss + sIdx) * N + col] = v;
                }
                __syncwarp();
            }
    }
}

// ------------------------- persistent GRU scan (one launch per layer) ----------
#define SCAN_SMEM_FLOATS (32*Hh + Hh + Hh + 8*1152 + 256 + 256 + 32 + 32 + 32)
#define SCAN_SMEM_BYTES  (SCAN_SMEM_FLOATS * 4)

__global__ void __launch_bounds__(256) gru_scan(
    const float* __restrict__ xz, const float* __restrict__ xr,
    const float* __restrict__ xg,
    const float* __restrict__ Whz, const float* __restrict__ Whr,
    const float* __restrict__ Whg,
    const float* __restrict__ bhz, const float* __restrict__ bhg,
    const float* __restrict__ h0l,
    float* __restrict__ hs, float* __restrict__ hTl)
{
    extern __shared__ float smem[];
    float* Wg   = smem;                  // [32][1024]
    float* swz  = Wg + 32 * Hh;          // [1024]
    float* swr  = swz + Hh;              // [1024]
    float* red  = swr + Hh;              // [8][32][36]
    float* zred = red + 8 * 1152;        // [8][32]
    float* rred = zred + 256;            // [8][32]
    float* zv   = rred + 256;            // [32]
    float* rv   = zv + 32;               // [32]
    float* bg   = rv + 32;               // [32]

    const int tid  = threadIdx.x;
    const int w    = tid >> 5, lane = tid & 31;
    const int bt   = blockIdx.x >> 5, nt = blockIdx.x & 31;
    const int b0   = bt * 32, j0 = nt * 32;

    for (int idx = tid; idx < 32 * Hh; idx += 256)
        Wg[idx] = Whg[(size_t)(j0 + (idx >> 10)) * Hh + (idx & 1023)];
    for (int idx = tid; idx < Hh; idx += 256) { swz[idx] = Whz[idx]; swr[idx] = Whr[idx]; }
    if (tid < 32) bg[tid] = bhg[j0 + tid];
    const float bz = bhz[0];

    for (int idx = blockIdx.x * 256 + tid; idx < Bb * Hh; idx += NBLK * 256) {
        int b = idx & 127, k = idx >> 7;
        g_ht[0][idx] = h0l[(size_t)b * (2 * Hh) + k];
    }
    grid_barrier();

    const int ju = tid >> 3;
    const int bq = (tid & 7) * 4;
    const int kbase = w * 128;
    const float4* Wg4 = (const float4*)Wg;
    int cur = 0;

#pragma unroll 1
    for (int s = 0; s < Ss; s++) {
        const float* ht_c = g_ht[cur];
        float* ht_n = g_ht[cur ^ 1];

        float4 ho = __ldcg((const float4*)(ht_c + (j0 + ju) * Bb + b0 + bq));
        float xgv[4];
#pragma unroll
        for (int i = 0; i < 4; i++)
            xgv[i] = xg[(size_t)(s * Bb + b0 + bq + i) * Hh + j0 + ju];

        float acc[32];
#pragma unroll
        for (int j = 0; j < 32; j++) acc[j] = 0.f;
        float zacc = 0.f, racc = 0.f;

        float h0v = __ldcg(ht_c + (kbase + 0) * Bb + b0 + lane);
        float h1v = __ldcg(ht_c + (kbase + 1) * Bb + b0 + lane);
        float h2v = __ldcg(ht_c + (kbase + 2) * Bb + b0 + lane);
        float h3v = __ldcg(ht_c + (kbase + 3) * Bb + b0 + lane);

#pragma unroll 4
        for (int q = 0; q < 32; q++) {
            float a0 = h0v, a1 = h1v, a2 = h2v, a3 = h3v;
            if (q < 31) {
                int kn = kbase + (q + 1) * 4;
                h0v = __ldcg(ht_c + (kn + 0) * Bb + b0 + lane);
                h1v = __ldcg(ht_c + (kn + 1) * Bb + b0 + lane);
                h2v = __ldcg(ht_c + (kn + 2) * Bb + b0 + lane);
                h3v = __ldcg(ht_c + (kn + 3) * Bb + b0 + lane);
            }
            int kq = (kbase >> 2) + q;
            float4 zq = ((const float4*)swz)[kq];
            float4 rq = ((const float4*)swr)[kq];
            zacc = fmaf(a0, zq.x, fmaf(a1, zq.y, fmaf(a2, zq.z, fmaf(a3, zq.w, zacc))));
            racc = fmaf(a0, rq.x, fmaf(a1, rq.y, fmaf(a2, rq.z, fmaf(a3, rq.w, racc))));
#pragma unroll
            for (int j = 0; j < 32; j++) {
                float4 wq = Wg4[j * 256 + kq];
                acc[j] = fmaf(a0, wq.x, fmaf(a1, wq.y, fmaf(a2, wq.z, fmaf(a3, wq.w, acc[j]))));
            }
        }

        zred[w * 32 + lane] = zacc;
        rred[w * 32 + lane] = racc;
        {
            float* rw = red + w * 1152;
#pragma unroll
            for (int j = 0; j < 32; j++) rw[j * 36 + lane] = acc[j];
        }
        __syncthreads();
        if (tid < 32) {
            float zs = 0.f, rs = 0.f;
#pragma unroll
            for (int ww = 0; ww < 8; ww++) { zs += zred[ww * 32 + tid]; rs += rred[ww * 32 + tid]; }
            float zval = xz[s * Bb + b0 + tid] + zs + bz;
            float rval = xr[s * Bb + b0 + tid] + rs;
            zv[tid] = 1.f / (1.f + expf(-zval));
            rv[tid] = 1.f / (1.f + expf(-rval));
        }
        __syncthreads();

        float m0 = 0.f, m1 = 0.f, m2 = 0.f, m3 = 0.f;
#pragma unroll
        for (int ww = 0; ww < 8; ww++) {
            float4 p = *(const float4*)(red + ww * 1152 + ju * 36 + bq);
            m0 += p.x; m1 += p.y; m2 += p.z; m3 += p.w;
        }
        float mm[4] = {m0, m1, m2, m3};
        float hof[4] = {ho.x, ho.y, ho.z, ho.w};
        float hn[4];
#pragma unroll
        for (int i = 0; i < 4; i++) {
            int bb = b0 + bq + i;
            float g = tanhf(xgv[i] + rv[bq + i] * mm[i] + bg[ju]);
            float zz = zv[bq + i];
            float v = zz * hof[i] + (1.f - zz) * g;
            hn[i] = v;
            hs[(size_t)(s * Bb + bb) * Hh + j0 + ju] = v;
        }
        __stcg((float4*)(ht_n + (j0 + ju) * Bb + b0 + bq),
               make_float4(hn[0], hn[1], hn[2], hn[3]));
        cur ^= 1;
        grid_barrier();
    }

    const float* ht_c = g_ht[cur];
#pragma unroll
    for (int i = 0; i < 4; i++)
        hTl[(size_t)(b0 + bq + i) * (2 * Hh) + j0 + ju] =
            __ldcg(ht_c + (j0 + ju) * Bb + b0 + bq + i);
}

// ------------------------- launcher -------------------------------------------
extern "C" void kernel_launch(void* const* d_in, const int* in_sizes, int n_in,
                              void* d_out, int out_size) {
    (void)in_sizes; (void)n_in; (void)out_size;

    const float* x    = (const float*)d_in[0];
    const float* h0   = (const float*)d_in[1];
    const float* Wxz0 = (const float*)d_in[2];
    const float* Whz0 = (const float*)d_in[3];
    const float* bhz0 = (const float*)d_in[4];
    const float* Wxr0 = (const float*)d_in[5];
    const float* bxr0 = (const float*)d_in[6];
    const float* Whr0 = (const float*)d_in[7];
    const float* Wxg0 = (const float*)d_in[8];
    const float* Whg0 = (const float*)d_in[9];
    const float* bhg0 = (const float*)d_in[10];
    const float* Wxz1 = (const float*)d_in[11];
    const float* Whz1 = (const float*)d_in[12];
    const float* bhz1 = (const float*)d_in[13];
    const float* Wxr1 = (const float*)d_in[14];
    const float* bxr1 = (const float*)d_in[15];
    const float* Whr1 = (const float*)d_in[16];
    const float* Wxg1 = (const float*)d_in[17];
    const float* Whg1 = (const float*)d_in[18];
    const float* bhg1 = (const float*)d_in[19];
    const float* Why  = (const float*)d_in[20];
    const float* bhy  = (const float*)d_in[21];

    float* out   = (float*)d_out;
    float* out_y = out;                                  // (B,S,O)
    float* out_h = out + (size_t)Bb * Ss * Oo;           // (B,2,H)

    float *xzp, *xrp, *xgp, *hsp;
    cudaGetSymbolAddress((void**)&xzp, g_xz);
    cudaGetSymbolAddress((void**)&xrp, g_xr);
    cudaGetSymbolAddress((void**)&xgp, g_xg);
    cudaGetSymbolAddress((void**)&hsp, g_hs);

    cudaFuncSetAttribute(gru_scan, cudaFuncAttributeMaxDynamicSharedMemorySize,
                         SCAN_SMEM_BYTES);
    cudaFuncSetAttribute(wgemm_tf32<0>, cudaFuncAttributeMaxDynamicSharedMemorySize,
                         WG_SMEM_BYTES);
    cudaFuncSetAttribute(wgemm_tf32<1>, cudaFuncAttributeMaxDynamicSharedMemorySize,
                         WG_SMEM_BYTES);

    const int M = Ss * Bb;                // 32768
    dim3 gemmBlk(256);
    dim3 gemmGridH(M / 128, Hh / 128);    // (256, 8)
    dim3 gemmGridO(M / 128, Oo / 128);    // (256, 2)
    int projBlocks = M / 8;

    // ----- layer 0 -----
    proj_zr<<<projBlocks, 256>>>(x, Wxz0, Wxr0, bxr0, xzp, xrp, Ii, 1);
    wgemm_tf32<0><<<gemmGridH, gemmBlk, WG_SMEM_BYTES>>>(x, Wxg0, xgp, Hh, Ii, 1, nullptr);
    gru_scan<<<NBLK, 256, SCAN_SMEM_BYTES>>>(
        xzp, xrp, xgp, Whz0, Whr0, Whg0, bhz0, bhg0,
        h0 + 0 * Hh, hsp, out_h + 0 * Hh);

    // ----- layer 1 -----
    proj_zr<<<projBlocks, 256>>>(hsp, Wxz1, Wxr1, bxr1, xzp, xrp, Hh, 0);
    wgemm_tf32<0><<<gemmGridH, gemmBlk, WG_SMEM_BYTES>>>(hsp, Wxg1, xgp, Hh, Hh, 0, nullptr);
    gru_scan<<<NBLK, 256, SCAN_SMEM_BYTES>>>(
        xzp, xrp, xgp, Whz1, Whr1, Whg1, bhz1, bhg1,
        h0 + 1 * Hh, hsp, out_h + 1 * Hh);

    // ----- output head: sigmoid(hs1 @ Why^T + bhy) -> (B,S,O) -----
    wgemm_tf32<1><<<gemmGridO, gemmBlk, WG_SMEM_BYTES>>>(hsp, Why, out_y, Oo, Hh, 0, bhy);
}

// round 11
// speedup vs baseline: 2.4005x; 1.5213x over previous
#include <cuda_runtime.h>
#include <mma.h>
#include <math.h>
#include <stdint.h>
#include <stddef.h>

using namespace nvcuda;

#define Bb 128
#define Ss 256
#define Ii 256
#define Hh 1024
#define Oo 256
#define NBLK 128

// ------------------------- device scratch (no allocations allowed) -------------
__device__ float g_xz[Ss * Bb];
__device__ float g_xr[Ss * Bb];
__device__ float g_xg[(size_t)Ss * Bb * Hh];   // 128 MB
__device__ float g_hs[(size_t)Ss * Bb * Hh];   // 128 MB
__device__ float g_ht[2][Hh * Bb];             // hidden state, k-major [k][b], dbl buf
__device__ unsigned g_bar_count;
__device__ volatile unsigned g_bar_gen;

// ------------------------- grid barrier (all NBLK CTAs resident) ---------------
__device__ __forceinline__ void grid_barrier() {
    __syncthreads();
    if (threadIdx.x == 0) {
        __threadfence();
        unsigned gen = g_bar_gen;
        unsigned t = atomicAdd(&g_bar_count, 1u);
        if (t == gridDim.x - 1) {
            g_bar_count = 0;
            __threadfence();
            g_bar_gen = gen + 1u;
        } else {
            while (g_bar_gen == gen) { __nanosleep(32); }
        }
        __threadfence();
    }
    __syncthreads();
}

// ------------------------- tf32 helpers ----------------------------------------
__device__ __forceinline__ uint32_t f2tf32(float v) {
    uint32_t u;
    asm("cvt.rna.tf32.f32 %0, %1;" : "=r"(u) : "f"(v));
    return u;
}
__device__ __forceinline__ void mma_tf32(float* d,
    uint32_t a0, uint32_t a1, uint32_t a2, uint32_t a3,
    uint32_t b0, uint32_t b1)
{
    asm volatile(
        "mma.sync.aligned.m16n8k8.row.col.f32.tf32.tf32.f32 "
        "{%0,%1,%2,%3}, {%4,%5,%6,%7}, {%8,%9}, {%0,%1,%2,%3};"
        : "+f"(d[0]), "+f"(d[1]), "+f"(d[2]), "+f"(d[3])
        : "r"(a0), "r"(a1), "r"(a2), "r"(a3), "r"(b0), "r"(b1));
}

// ------------------------- scalar-gate projections ----------------------------
__global__ void __launch_bounds__(256) proj_zr(
    const float* __restrict__ A, const float* __restrict__ Wxz,
    const float* __restrict__ Wxr, const float* __restrict__ bxr,
    float* __restrict__ xz, float* __restrict__ xr, int K, int amode)
{
    int warp = blockIdx.x * (blockDim.x >> 5) + (threadIdx.x >> 5);
    int lane = threadIdx.x & 31;
    const float* row;
    if (amode) {
        int s = warp >> 7, b = warp & 127;
        row = A + ((size_t)b * Ss + s) * K;
    } else {
        row = A + (size_t)warp * K;
    }
    float az = 0.f, ar = 0.f;
    for (int k = lane; k < K; k += 32) {
        float v = row[k];
        az = fmaf(v, Wxz[k], az);
        ar = fmaf(v, Wxr[k], ar);
    }
#pragma unroll
    for (int d = 16; d; d >>= 1) {
        az += __shfl_down_sync(0xffffffffu, az, d);
        ar += __shfl_down_sync(0xffffffffu, ar, d);
    }
    if (lane == 0) { xz[warp] = az; xr[warp] = ar + bxr[0]; }
}

// ------------------------- tf32 WMMA GEMM v2 (unchanged, r10 WIN) ---------------
#define GLD 36
#define GSTG (128 * GLD * 2)
#define WG_SMEM_BYTES (2 * GSTG * 4)

template <int EPI>
__global__ void __launch_bounds__(256) wgemm_tf32(
    const float* __restrict__ A, const float* __restrict__ Bw,
    float* __restrict__ C, int N, int K, int amode,
    const float* __restrict__ bias)
{
    extern __shared__ float sm[];

    const int tid = threadIdx.x;
    const int m0 = blockIdx.x * 128;
    const int n0 = blockIdx.y * 128;

    const int lrow = tid >> 3;
    const int lc4  = (tid & 7) * 4;

    const float* aP[4];
    const float* bP[4];
#pragma unroll
    for (int i = 0; i < 4; i++) {
        int r  = lrow + 32 * i;
        int ar = m0 + r;
        if (amode) {
            int s = ar >> 7, b = ar & 127;
            aP[i] = A + ((size_t)b * Ss + s) * K;
        } else {
            aP[i] = A + (size_t)ar * K;
        }
        bP[i] = Bw + (size_t)(n0 + r) * K;
    }

    const int w    = tid >> 5;
    const int wr   = w >> 1;
    const int wc   = w & 1;
    const int lane = tid & 31;

    wmma::fragment<wmma::accumulator, 16, 16, 8, float> cf[2][4];
#pragma unroll
    for (int i = 0; i < 2; i++)
#pragma unroll
        for (int j = 0; j < 4; j++) wmma::fill_fragment(cf[i][j], 0.0f);

    float4 av[4], bv[4];
#pragma unroll
    for (int i = 0; i < 4; i++) {
        av[i] = *(const float4*)(aP[i] + lc4);
        bv[i] = *(const float4*)(bP[i] + lc4);
    }

    int cur = 0;
#pragma unroll 1
    for (int k0 = 0; k0 < K; k0 += 32) {
        float* sa = sm + cur * GSTG;
        float* sb = sa + 128 * GLD;
#pragma unroll
        for (int i = 0; i < 4; i++) {
            int row = lrow + 32 * i;
            float* pa = sa + row * GLD + lc4;
            pa[0] = wmma::__float_to_tf32(av[i].x);
            pa[1] = wmma::__float_to_tf32(av[i].y);
            pa[2] = wmma::__float_to_tf32(av[i].z);
            pa[3] = wmma::__float_to_tf32(av[i].w);
            float* pb = sb + row * GLD + lc4;
            pb[0] = wmma::__float_to_tf32(bv[i].x);
            pb[1] = wmma::__float_to_tf32(bv[i].y);
            pb[2] = wmma::__float_to_tf32(bv[i].z);
            pb[3] = wmma::__float_to_tf32(bv[i].w);
        }
        __syncthreads();
        if (k0 + 32 < K) {
#pragma unroll
            for (int i = 0; i < 4; i++) {
                av[i] = *(const float4*)(aP[i] + k0 + 32 + lc4);
                bv[i] = *(const float4*)(bP[i] + k0 + 32 + lc4);
            }
        }
        const float* sa_r = sa + (wr * 32) * GLD;
        const float* sb_r = sb + (wc * 64) * GLD;
#pragma unroll
        for (int kk = 0; kk < 32; kk += 8) {
            wmma::fragment<wmma::matrix_a, 16, 16, 8, wmma::precision::tf32,
                           wmma::row_major> af[2];
            wmma::fragment<wmma::matrix_b, 16, 16, 8, wmma::precision::tf32,
                           wmma::col_major> bf[4];
            wmma::load_matrix_sync(af[0], sa_r + kk, GLD);
            wmma::load_matrix_sync(af[1], sa_r + 16 * GLD + kk, GLD);
#pragma unroll
            for (int j = 0; j < 4; j++)
                wmma::load_matrix_sync(bf[j], sb_r + j * 16 * GLD + kk, GLD);
#pragma unroll
            for (int i = 0; i < 2; i++)
#pragma unroll
                for (int j = 0; j < 4; j++)
                    wmma::mma_sync(cf[i][j], af[i], bf[j], cf[i][j]);
        }
        cur ^= 1;
    }

    if (EPI == 0) {
#pragma unroll
        for (int i = 0; i < 2; i++)
#pragma unroll
            for (int j = 0; j < 4; j++)
                wmma::store_matrix_sync(
                    &C[(size_t)(m0 + wr * 32 + i * 16) * N + n0 + wc * 64 + j * 16],
                    cf[i][j], N, wmma::mem_row_major);
    } else {
        __syncthreads();
        float* patch = sm + w * 320;
        const int sIdx = m0 >> 7;
#pragma unroll
        for (int i = 0; i < 2; i++)
#pragma unroll
            for (int j = 0; j < 4; j++) {
                wmma::store_matrix_sync(patch, cf[i][j], 20, wmma::mem_row_major);
                __syncwarp();
                int colb = n0 + wc * 64 + j * 16;
                int rowb = wr * 32 + i * 16;
#pragma unroll
                for (int e = 0; e < 8; e++) {
                    int idx = lane * 8 + e;
                    int pr = idx >> 4, pc = idx & 15;
                    int b = rowb + pr;
                    int col = colb + pc;
                    float v = patch[pr * 20 + pc] + bias[col];
                    v = 1.f / (1.f + expf(-v));
                    C[((size_t)b * Ss + sIdx) * N + col] = v;
                }
                __syncwarp();
            }
    }
}

// ------------------------- persistent GRU scan: tensor-core matvec --------------
// grid = 128 CTAs: bt (4 b-tiles of 32) x nt (32 j-tiles of 32). Warp w owns
// k in [w*128,(w+1)*128). Whg slice pre-swizzled ONCE into mma-fragment order
// (tf32) in smem; h read per step via ldcg directly into mma A fragments
// (k-major layout -> each LDG covers 4x32B sectors, zero duplication).
// z/r scalar dots ride the same loaded h values as fp32 FFMA side-channels.
#define SCAN_SMEM_FLOATS (32*Hh + Hh + Hh + 8*1152 + 256 + 256 + 32 + 32 + 32)
#define SCAN_SMEM_BYTES  (SCAN_SMEM_FLOATS * 4)

__global__ void __launch_bounds__(256) gru_scan(
    const float* __restrict__ xz, const float* __restrict__ xr,
    const float* __restrict__ xg,
    const float* __restrict__ Whz, const float* __restrict__ Whr,
    const float* __restrict__ Whg,
    const float* __restrict__ bhz, const float* __restrict__ bhg,
    const float* __restrict__ h0l,
    float* __restrict__ hs, float* __restrict__ hTl)
{
    extern __shared__ float smem[];
    float* wfrag = smem;                 // [32*Hh] fragment-swizzled tf32 Whg slice
    float* swz   = wfrag + 32 * Hh;      // [1024] fp32
    float* swr   = swz + Hh;             // [1024] fp32
    float* red   = swr + Hh;             // [8][32][36]
    float* zred  = red + 8 * 1152;       // [8][32]
    float* rred  = zred + 256;           // [8][32]
    float* zv    = rred + 256;           // [32]
    float* rv    = zv + 32;              // [32]
    float* bg    = rv + 32;              // [32]

    const int tid  = threadIdx.x;
    const int w    = tid >> 5, lane = tid & 31;
    const int g    = lane >> 2, t4 = lane & 3;
    const int bt   = blockIdx.x >> 5, nt = blockIdx.x & 31;
    const int b0   = bt * 32, j0 = nt * 32;

    // W fragment swizzle + tf32 convert (once):
    // slot idx = wk*256 + nf*64 + l*2 + c  ->  W[j0 + nf*8 + (l>>2)][wk*8 + (l&3) + c*4]
    for (int idx = tid; idx < 32 * Hh; idx += 256) {
        int c  = idx & 1;
        int l  = (idx >> 1) & 31;
        int nf = (idx >> 6) & 3;
        int wk = idx >> 8;
        int k  = wk * 8 + (l & 3) + c * 4;
        int j  = j0 + nf * 8 + (l >> 2);
        wfrag[idx] = __uint_as_float(f2tf32(Whg[(size_t)j * Hh + k]));
    }
    for (int idx = tid; idx < Hh; idx += 256) { swz[idx] = Whz[idx]; swr[idx] = Whr[idx]; }
    if (tid < 32) bg[tid] = bhg[j0 + tid];
    const float bz = bhz[0];

    for (int idx = blockIdx.x * 256 + tid; idx < Bb * Hh; idx += NBLK * 256) {
        int b = idx & 127, k = idx >> 7;
        g_ht[0][idx] = h0l[(size_t)b * (2 * Hh) + k];
    }
    grid_barrier();

    const int ju = tid >> 3;
    const int bq = (tid & 7) * 4;
    // per-lane bases
    const float* wpL = wfrag + w * 4096 + lane * 2;   // warp's fragment block
    int cur = 0;

#pragma unroll 1
    for (int s = 0; s < Ss; s++) {
        const float* ht_c = g_ht[cur];
        float* ht_n = g_ht[cur ^ 1];

        // prefetch update-phase operands
        float4 ho = __ldcg((const float4*)(ht_c + (j0 + ju) * Bb + b0 + bq));
        float xgv[4];
#pragma unroll
        for (int i = 0; i < 4; i++)
            xgv[i] = xg[(size_t)(s * Bb + b0 + bq + i) * Hh + j0 + ju];

        // --- tensor matvec: acc[mf][nf][4], A from ldcg, B from swizzled smem
        float acc[2][4][4];
#pragma unroll
        for (int mf = 0; mf < 2; mf++)
#pragma unroll
            for (int nf = 0; nf < 4; nf++)
#pragma unroll
                for (int e = 0; e < 4; e++) acc[mf][nf][e] = 0.f;

        float zacc[4] = {0.f, 0.f, 0.f, 0.f};
        float racc[4] = {0.f, 0.f, 0.f, 0.f};

        const float* ap = ht_c + (size_t)(w * 128 + t4) * Bb + b0 + g;

#pragma unroll 4
        for (int kf = 0; kf < 16; kf++) {
            float ar[8];
            const float* a = ap + kf * 1024;
            ar[0] = __ldcg(a + 0);    // (k=t4,   b=g)
            ar[1] = __ldcg(a + 8);    // (k=t4,   b=g+8)
            ar[2] = __ldcg(a + 16);   // (k=t4,   b=g+16)
            ar[3] = __ldcg(a + 24);   // (k=t4,   b=g+24)
            ar[4] = __ldcg(a + 512);  // (k=t4+4, b=g)
            ar[5] = __ldcg(a + 520);
            ar[6] = __ldcg(a + 528);
            ar[7] = __ldcg(a + 536);

            // z/r side-channel (raw fp32)
            int kk = w * 128 + kf * 8 + t4;
            float wz0 = swz[kk], wz4 = swz[kk + 4];
            float wr0 = swr[kk], wr4 = swr[kk + 4];
            zacc[0] = fmaf(ar[0], wz0, fmaf(ar[4], wz4, zacc[0]));
            zacc[1] = fmaf(ar[1], wz0, fmaf(ar[5], wz4, zacc[1]));
            zacc[2] = fmaf(ar[2], wz0, fmaf(ar[6], wz4, zacc[2]));
            zacc[3] = fmaf(ar[3], wz0, fmaf(ar[7], wz4, zacc[3]));
            racc[0] = fmaf(ar[0], wr0, fmaf(ar[4], wr4, racc[0]));
            racc[1] = fmaf(ar[1], wr0, fmaf(ar[5], wr4, racc[1]));
            racc[2] = fmaf(ar[2], wr0, fmaf(ar[6], wr4, racc[2]));
            racc[3] = fmaf(ar[3], wr0, fmaf(ar[7], wr4, racc[3]));

            uint32_t at[8];
#pragma unroll
            for (int i = 0; i < 8; i++) at[i] = f2tf32(ar[i]);

#pragma unroll
            for (int nf = 0; nf < 4; nf++) {
                float2 bv = *(const float2*)(wpL + kf * 256 + nf * 64);
                uint32_t bx = __float_as_uint(bv.x);
                uint32_t by = __float_as_uint(bv.y);
                // mf0: b rows g..g+15 -> A regs {ar0, ar1, ar4, ar5}
                mma_tf32(acc[0][nf], at[0], at[1], at[4], at[5], bx, by);
                // mf1: b rows g+16..g+31 -> A regs {ar2, ar3, ar6, ar7}
                mma_tf32(acc[1][nf], at[2], at[3], at[6], at[7], bx, by);
            }
        }

        // --- epilogue: c-frags -> red[w][j][36+b] (conflict-free permutation)
        {
            float* rp = red + w * 1152;
#pragma unroll
            for (int mf = 0; mf < 2; mf++)
#pragma unroll
                for (int nf = 0; nf < 4; nf++) {
                    int jl = nf * 8 + 2 * t4;
                    int bl = mf * 16 + g;
                    rp[jl * 36 + bl]           = acc[mf][nf][0];
                    rp[(jl + 1) * 36 + bl]     = acc[mf][nf][1];
                    rp[jl * 36 + bl + 8]       = acc[mf][nf][2];
                    rp[(jl + 1) * 36 + bl + 8] = acc[mf][nf][3];
                }
        }
        // z/r quad reduction (lanes of a quad cover all k residues)
#pragma unroll
        for (int i = 0; i < 4; i++) {
            zacc[i] += __shfl_xor_sync(0xffffffffu, zacc[i], 1);
            zacc[i] += __shfl_xor_sync(0xffffffffu, zacc[i], 2);
            racc[i] += __shfl_xor_sync(0xffffffffu, racc[i], 1);
            racc[i] += __shfl_xor_sync(0xffffffffu, racc[i], 2);
        }
        if (t4 == 0) {
            zred[w * 32 + g]      = zacc[0];
            zred[w * 32 + g + 8]  = zacc[1];
            zred[w * 32 + g + 16] = zacc[2];
            zred[w * 32 + g + 24] = zacc[3];
            rred[w * 32 + g]      = racc[0];
            rred[w * 32 + g + 8]  = racc[1];
            rred[w * 32 + g + 16] = racc[2];
            rred[w * 32 + g + 24] = racc[3];
        }
        __syncthreads();
        if (tid < 32) {
            float zs = 0.f, rs = 0.f;
#pragma unroll
            for (int ww = 0; ww < 8; ww++) { zs += zred[ww * 32 + tid]; rs += rred[ww * 32 + tid]; }
            float zval = xz[s * Bb + b0 + tid] + zs + bz;
            float rval = xr[s * Bb + b0 + tid] + rs;
            zv[tid] = 1.f / (1.f + expf(-zval));
            rv[tid] = 1.f / (1.f + expf(-rval));
        }
        __syncthreads();

        float m0 = 0.f, m1 = 0.f, m2 = 0.f, m3 = 0.f;
#pragma unroll
        for (int ww = 0; ww < 8; ww++) {
            float4 p = *(const float4*)(red + ww * 1152 + ju * 36 + bq);
            m0 += p.x; m1 += p.y; m2 += p.z; m3 += p.w;
        }
        float mm[4] = {m0, m1, m2, m3};
        float hof[4] = {ho.x, ho.y, ho.z, ho.w};
        float hn[4];
#pragma unroll
        for (int i = 0; i < 4; i++) {
            int bb = b0 + bq + i;
            float gg = tanhf(xgv[i] + rv[bq + i] * mm[i] + bg[ju]);
            float zz = zv[bq + i];
            float v = zz * hof[i] + (1.f - zz) * gg;
            hn[i] = v;
            hs[(size_t)(s * Bb + bb) * Hh + j0 + ju] = v;
        }
        __stcg((float4*)(ht_n + (j0 + ju) * Bb + b0 + bq),
               make_float4(hn[0], hn[1], hn[2], hn[3]));
        cur ^= 1;
        grid_barrier();
    }

    const float* ht_c = g_ht[cur];
#pragma unroll
    for (int i = 0; i < 4; i++)
        hTl[(size_t)(b0 + bq + i) * (2 * Hh) + j0 + ju] =
            __ldcg(ht_c + (j0 + ju) * Bb + b0 + bq + i);
}

// ------------------------- launcher -------------------------------------------
extern "C" void kernel_launch(void* const* d_in, const int* in_sizes, int n_in,
                              void* d_out, int out_size) {
    (void)in_sizes; (void)n_in; (void)out_size;

    const float* x    = (const float*)d_in[0];
    const float* h0   = (const float*)d_in[1];
    const float* Wxz0 = (const float*)d_in[2];
    const float* Whz0 = (const float*)d_in[3];
    const float* bhz0 = (const float*)d_in[4];
    const float* Wxr0 = (const float*)d_in[5];
    const float* bxr0 = (const float*)d_in[6];
    const float* Whr0 = (const float*)d_in[7];
    const float* Wxg0 = (const float*)d_in[8];
    const float* Whg0 = (const float*)d_in[9];
    const float* bhg0 = (const float*)d_in[10];
    const float* Wxz1 = (const float*)d_in[11];
    const float* Whz1 = (const float*)d_in[12];
    const float* bhz1 = (const float*)d_in[13];
    const float* Wxr1 = (const float*)d_in[14];
    const float* bxr1 = (const float*)d_in[15];
    const float* Whr1 = (const float*)d_in[16];
    const float* Wxg1 = (const float*)d_in[17];
    const float* Whg1 = (const float*)d_in[18];
    const float* bhg1 = (const float*)d_in[19];
    const float* Why  = (const float*)d_in[20];
    const float* bhy  = (const float*)d_in[21];

    float* out   = (float*)d_out;
    float* out_y = out;                                  // (B,S,O)
    float* out_h = out + (size_t)Bb * Ss * Oo;           // (B,2,H)

    float *xzp, *xrp, *xgp, *hsp;
    cudaGetSymbolAddress((void**)&xzp, g_xz);
    cudaGetSymbolAddress((void**)&xrp, g_xr);
    cudaGetSymbolAddress((void**)&xgp, g_xg);
    cudaGetSymbolAddress((void**)&hsp, g_hs);

    cudaFuncSetAttribute(gru_scan, cudaFuncAttributeMaxDynamicSharedMemorySize,
                         SCAN_SMEM_BYTES);
    cudaFuncSetAttribute(wgemm_tf32<0>, cudaFuncAttributeMaxDynamicSharedMemorySize,
                         WG_SMEM_BYTES);
    cudaFuncSetAttribute(wgemm_tf32<1>, cudaFuncAttributeMaxDynamicSharedMemorySize,
                         WG_SMEM_BYTES);

    const int M = Ss * Bb;                // 32768
    dim3 gemmBlk(256);
    dim3 gemmGridH(M / 128, Hh / 128);    // (256, 8)
    dim3 gemmGridO(M / 128, Oo / 128);    // (256, 2)
    int projBlocks = M / 8;

    // ----- layer 0 -----
    proj_zr<<<projBlocks, 256>>>(x, Wxz0, Wxr0, bxr0, xzp, xrp, Ii, 1);
    wgemm_tf32<0><<<gemmGridH, gemmBlk, WG_SMEM_BYTES>>>(x, Wxg0, xgp, Hh, Ii, 1, nullptr);
    gru_scan<<<NBLK, 256, SCAN_SMEM_BYTES>>>(
        xzp, xrp, xgp, Whz0, Whr0, Whg0, bhz0, bhg0,
        h0 + 0 * Hh, hsp, out_h + 0 * Hh);

    // ----- layer 1 -----
    proj_zr<<<projBlocks, 256>>>(hsp, Wxz1, Wxr1, bxr1, xzp, xrp, Hh, 0);
    wgemm_tf32<0><<<gemmGridH, gemmBlk, WG_SMEM_BYTES>>>(hsp, Wxg1, xgp, Hh, Hh, 0, nullptr);
    gru_scan<<<NBLK, 256, SCAN_SMEM_BYTES>>>(
        xzp, xrp, xgp, Whz1, Whr1, Whg1, bhz1, bhg1,
        h0 + 1 * Hh, hsp, out_h + 1 * Hh);

    // ----- output head: sigmoid(hs1 @ Why^T + bhy) -> (B,S,O) -----
    wgemm_tf32<1><<<gemmGridO, gemmBlk, WG_SMEM_BYTES>>>(hsp, Why, out_y, Oo, Hh, 0, bhy);
}

// round 12
// speedup vs baseline: 2.4070x; 1.0027x over previous
#include <cuda_runtime.h>
#include <math.h>
#include <stdint.h>
#include <stddef.h>

#define Bb 128
#define Ss 256
#define Ii 256
#define Hh 1024
#define Oo 256
#define NBLK 128

// ------------------------- device scratch (no allocations allowed) -------------
__device__ float g_xz[Ss * Bb];
__device__ float g_xr[Ss * Bb];
__device__ float g_xg[(size_t)Ss * Bb * Hh];   // 128 MB
__device__ float g_hs[(size_t)Ss * Bb * Hh];   // 128 MB
__device__ float g_ht[2][Hh * Bb];             // hidden state, k-major [k][b], dbl buf
__device__ unsigned g_bar_count;
__device__ volatile unsigned g_bar_gen;

// ------------------------- grid barrier (all NBLK CTAs resident) ---------------
__device__ __forceinline__ void grid_barrier() {
    __syncthreads();
    if (threadIdx.x == 0) {
        __threadfence();
        unsigned gen = g_bar_gen;
        unsigned t = atomicAdd(&g_bar_count, 1u);
        if (t == gridDim.x - 1) {
            g_bar_count = 0;
            __threadfence();
            g_bar_gen = gen + 1u;
        } else {
            while (g_bar_gen == gen) { __nanosleep(32); }
        }
        __threadfence();
    }
    __syncthreads();
}

// ------------------------- tf32 / mma helpers ----------------------------------
__device__ __forceinline__ uint32_t f2tf32(float v) {
    uint32_t u;
    asm("cvt.rna.tf32.f32 %0, %1;" : "=r"(u) : "f"(v));
    return u;
}
__device__ __forceinline__ void mma_tf32(float* d,
    uint32_t a0, uint32_t a1, uint32_t a2, uint32_t a3,
    uint32_t b0, uint32_t b1)
{
    asm volatile(
        "mma.sync.aligned.m16n8k8.row.col.f32.tf32.tf32.f32 "
        "{%0,%1,%2,%3}, {%4,%5,%6,%7}, {%8,%9}, {%0,%1,%2,%3};"
        : "+f"(d[0]), "+f"(d[1]), "+f"(d[2]), "+f"(d[3])
        : "r"(a0), "r"(a1), "r"(a2), "r"(a3), "r"(b0), "r"(b1));
}
__device__ __forceinline__ float sigf(float v) {
    return 1.f / (1.f + expf(-v));
}

// ------------------------- scalar-gate projections ----------------------------
__global__ void __launch_bounds__(256) proj_zr(
    const float* __restrict__ A, const float* __restrict__ Wxz,
    const float* __restrict__ Wxr, const float* __restrict__ bxr,
    float* __restrict__ xz, float* __restrict__ xr, int K, int amode)
{
    int warp = blockIdx.x * (blockDim.x >> 5) + (threadIdx.x >> 5);
    int lane = threadIdx.x & 31;
    const float* row;
    if (amode) {
        int s = warp >> 7, b = warp & 127;
        row = A + ((size_t)b * Ss + s) * K;
    } else {
        row = A + (size_t)warp * K;
    }
    float az = 0.f, ar = 0.f;
    for (int k = lane; k < K; k += 32) {
        float v = row[k];
        az = fmaf(v, Wxz[k], az);
        ar = fmaf(v, Wxr[k], ar);
    }
#pragma unroll
    for (int d = 16; d; d >>= 1) {
        az += __shfl_down_sync(0xffffffffu, az, d);
        ar += __shfl_down_sync(0xffffffffu, ar, d);
    }
    if (lane == 0) { xz[warp] = az; xr[warp] = ar + bxr[0]; }
}

// ------------------------- raw-mma tf32 GEMM v3 --------------------------------
// C[r,n] = sum_k Arow(r)[k] * Bw[n,k]. 128x128 tile, kstep 32, double-buffered
// fragment-swizzled smem (tf32 converted at staging, STS.128), raw m16n8k8 mma,
// C-fragments written directly to gmem (STG.64). 8 warps: warp (wr,wc) = 32m x 64n.
// EPI==0: C row-major. EPI==1: sigmoid(v + bias[n]) scattered to (B,S,N).
#define WGA_FLOATS 4096
#define WG_STAGE   8192                 // A(4096) + B(4096) floats per stage
#define WG_SMEM_BYTES (2 * WG_STAGE * 4)   // 65536 B

template <int EPI>
__global__ void __launch_bounds__(256) wgemm_tf32(
    const float* __restrict__ A, const float* __restrict__ Bw,
    float* __restrict__ C, int N, int K, int amode,
    const float* __restrict__ bias)
{
    extern __shared__ float sm[];

    const int tid = threadIdx.x;
    const int m0 = blockIdx.x * 128;
    const int n0 = blockIdx.y * 128;
    const int lane = tid & 31;
    const int w  = tid >> 5;
    const int wr = w >> 1;              // m offset wr*32
    const int wc = w & 1;               // n offset wc*64

    // ---- staging role: this thread owns row `mrow` (both A and B slabs) at
    //      kf0 = tid>>7 and kf0+2 (kf = 8-k fragment index within 32-k slab)
    const int mrow = tid & 127;
    const int kf0  = tid >> 7;          // 0 or 1 (other slot: +2)

    const float* aRow;
    {
        int ar = m0 + mrow;
        if (amode) {
            int s = ar >> 7, b = ar & 127;
            aRow = A + ((size_t)b * Ss + s) * K;
        } else {
            aRow = A + (size_t)ar * K;
        }
    }
    const float* bRow = Bw + (size_t)(n0 + mrow) * K;

    // fragment-layout smem offsets (floats):
    //   A pair-block: ((kf*8 + mf)*2 + pair)*64 + (m&7)*8
    //   B block:      WGA_FLOATS + (kf*16 + nf)*64 + (n&7)*8
    const int mf_s   = mrow >> 4;
    const int pair_s = (mrow >> 3) & 1;
    const int offA0  = ((kf0 * 8 + mf_s) * 2 + pair_s) * 64 + (mrow & 7) * 8;
    const int offA1  = (((kf0 + 2) * 8 + mf_s) * 2 + pair_s) * 64 + (mrow & 7) * 8;
    const int offB0  = WGA_FLOATS + (kf0 * 16 + (mrow >> 3)) * 64 + (mrow & 7) * 8;
    const int offB1  = WGA_FLOATS + ((kf0 + 2) * 16 + (mrow >> 3)) * 64 + (mrow & 7) * 8;

    float acc[2][8][4];
#pragma unroll
    for (int i = 0; i < 2; i++)
#pragma unroll
        for (int j = 0; j < 8; j++)
#pragma unroll
            for (int e = 0; e < 4; e++) acc[i][j][e] = 0.f;

    // prefetch slab 0: per slot two float4 (k..k+3, k+4..k+7)
    float4 au[2], av[2], bu[2], bv[2];
    {
        int ka = kf0 * 8, kb = (kf0 + 2) * 8;
        au[0] = *(const float4*)(aRow + ka);     av[0] = *(const float4*)(aRow + ka + 4);
        au[1] = *(const float4*)(aRow + kb);     av[1] = *(const float4*)(aRow + kb + 4);
        bu[0] = *(const float4*)(bRow + ka);     bv[0] = *(const float4*)(bRow + ka + 4);
        bu[1] = *(const float4*)(bRow + kb);     bv[1] = *(const float4*)(bRow + kb + 4);
    }

    int cur = 0;
#pragma unroll 1
    for (int k0 = 0; k0 < K; k0 += 32) {
        float* buf = sm + cur * WG_STAGE;

        // ---- store staged slab in fragment order, tf32-converted, STS.128
#pragma unroll
        for (int i = 0; i < 2; i++) {
            float4 u = au[i], v = av[i];
            float4 s0 = make_float4(
                __uint_as_float(f2tf32(u.x)), __uint_as_float(f2tf32(v.x)),
                __uint_as_float(f2tf32(u.y)), __uint_as_float(f2tf32(v.y)));
            float4 s1 = make_float4(
                __uint_as_float(f2tf32(u.z)), __uint_as_float(f2tf32(v.z)),
                __uint_as_float(f2tf32(u.w)), __uint_as_float(f2tf32(v.w)));
            int off = i ? offA1 : offA0;
            *(float4*)(buf + off)     = s0;
            *(float4*)(buf + off + 4) = s1;

            u = bu[i]; v = bv[i];
            s0 = make_float4(
                __uint_as_float(f2tf32(u.x)), __uint_as_float(f2tf32(v.x)),
                __uint_as_float(f2tf32(u.y)), __uint_as_float(f2tf32(v.y)));
            s1 = make_float4(
                __uint_as_float(f2tf32(u.z)), __uint_as_float(f2tf32(v.z)),
                __uint_as_float(f2tf32(u.w)), __uint_as_float(f2tf32(v.w)));
            off = i ? offB1 : offB0;
            *(float4*)(buf + off)     = s0;
            *(float4*)(buf + off + 4) = s1;
        }
        __syncthreads();

        if (k0 + 32 < K) {   // prefetch next slab behind this stage's compute
            int ka = k0 + 32 + kf0 * 8, kb = k0 + 32 + (kf0 + 2) * 8;
            au[0] = *(const float4*)(aRow + ka);  av[0] = *(const float4*)(aRow + ka + 4);
            au[1] = *(const float4*)(aRow + kb);  av[1] = *(const float4*)(aRow + kb + 4);
            bu[0] = *(const float4*)(bRow + ka);  bv[0] = *(const float4*)(bRow + ka + 4);
            bu[1] = *(const float4*)(bRow + kb);  bv[1] = *(const float4*)(bRow + kb + 4);
        }

        // ---- compute: conflict-free LDS.64 fragment loads + raw mma
        const float* bufB = buf + WGA_FLOATS;
#pragma unroll
        for (int kf = 0; kf < 4; kf++) {
            uint32_t a[2][4];
#pragma unroll
            for (int mfi = 0; mfi < 2; mfi++) {
                const float* base = buf + ((kf * 8 + wr * 2 + mfi) * 2) * 64 + lane * 2;
                float2 p0 = *(const float2*)(base);
                float2 p1 = *(const float2*)(base + 64);
                a[mfi][0] = __float_as_uint(p0.x);   // (m, k)
                a[mfi][1] = __float_as_uint(p1.x);   // (m+8, k)
                a[mfi][2] = __float_as_uint(p0.y);   // (m, k+4)
                a[mfi][3] = __float_as_uint(p1.y);   // (m+8, k+4)
            }
#pragma unroll
            for (int nfj = 0; nfj < 8; nfj++) {
                float2 bf = *(const float2*)(bufB + (kf * 16 + wc * 8 + nfj) * 64 + lane * 2);
                uint32_t b0 = __float_as_uint(bf.x);
                uint32_t b1 = __float_as_uint(bf.y);
                mma_tf32(acc[0][nfj], a[0][0], a[0][1], a[0][2], a[0][3], b0, b1);
                mma_tf32(acc[1][nfj], a[1][0], a[1][1], a[1][2], a[1][3], b0, b1);
            }
        }
        cur ^= 1;
    }

    // ---- epilogue: c-frags straight to gmem
    const int g = lane >> 2, t4 = lane & 3;
    if (EPI == 0) {
#pragma unroll
        for (int mfi = 0; mfi < 2; mfi++) {
            int mrow0 = m0 + wr * 32 + mfi * 16 + g;
#pragma unroll
            for (int nfj = 0; nfj < 8; nfj++) {
                int nb = n0 + wc * 64 + nfj * 8 + 2 * t4;
                *(float2*)&C[(size_t)mrow0 * N + nb] =
                    make_float2(acc[mfi][nfj][0], acc[mfi][nfj][1]);
                *(float2*)&C[(size_t)(mrow0 + 8) * N + nb] =
                    make_float2(acc[mfi][nfj][2], acc[mfi][nfj][3]);
            }
        }
    } else {
        const int sIdx = m0 >> 7;    // s constant within the M-tile; b = m-local
#pragma unroll
        for (int mfi = 0; mfi < 2; mfi++) {
            int bl = wr * 32 + mfi * 16 + g;
#pragma unroll
            for (int nfj = 0; nfj < 8; nfj++) {
                int nb = n0 + wc * 64 + nfj * 8 + 2 * t4;
                float bs0 = bias[nb], bs1 = bias[nb + 1];
                *(float2*)&C[((size_t)bl * Ss + sIdx) * N + nb] =
                    make_float2(sigf(acc[mfi][nfj][0] + bs0),
                                sigf(acc[mfi][nfj][1] + bs1));
                *(float2*)&C[((size_t)(bl + 8) * Ss + sIdx) * N + nb] =
                    make_float2(sigf(acc[mfi][nfj][2] + bs0),
                                sigf(acc[mfi][nfj][3] + bs1));
            }
        }
    }
}

// ------------------------- persistent GRU scan (r11 WIN, unchanged) ------------
#define SCAN_SMEM_FLOATS (32*Hh + Hh + Hh + 8*1152 + 256 + 256 + 32 + 32 + 32)
#define SCAN_SMEM_BYTES  (SCAN_SMEM_FLOATS * 4)

__global__ void __launch_bounds__(256) gru_scan(
    const float* __restrict__ xz, const float* __restrict__ xr,
    const float* __restrict__ xg,
    const float* __restrict__ Whz, const float* __restrict__ Whr,
    const float* __restrict__ Whg,
    const float* __restrict__ bhz, const float* __restrict__ bhg,
    const float* __restrict__ h0l,
    float* __restrict__ hs, float* __restrict__ hTl)
{
    extern __shared__ float smem[];
    float* wfrag = smem;
    float* swz   = wfrag + 32 * Hh;
    float* swr   = swz + Hh;
    float* red   = swr + Hh;
    float* zred  = red + 8 * 1152;
    float* rred  = zred + 256;
    float* zv    = rred + 256;
    float* rv    = zv + 32;
    float* bg    = rv + 32;

    const int tid  = threadIdx.x;
    const int w    = tid >> 5, lane = tid & 31;
    const int g    = lane >> 2, t4 = lane & 3;
    const int bt   = blockIdx.x >> 5, nt = blockIdx.x & 31;
    const int b0   = bt * 32, j0 = nt * 32;

    for (int idx = tid; idx < 32 * Hh; idx += 256) {
        int c  = idx & 1;
        int l  = (idx >> 1) & 31;
        int nf = (idx >> 6) & 3;
        int wk = idx >> 8;
        int k  = wk * 8 + (l & 3) + c * 4;
        int j  = j0 + nf * 8 + (l >> 2);
        wfrag[idx] = __uint_as_float(f2tf32(Whg[(size_t)j * Hh + k]));
    }
    for (int idx = tid; idx < Hh; idx += 256) { swz[idx] = Whz[idx]; swr[idx] = Whr[idx]; }
    if (tid < 32) bg[tid] = bhg[j0 + tid];
    const float bz = bhz[0];

    for (int idx = blockIdx.x * 256 + tid; idx < Bb * Hh; idx += NBLK * 256) {
        int b = idx & 127, k = idx >> 7;
        g_ht[0][idx] = h0l[(size_t)b * (2 * Hh) + k];
    }
    grid_barrier();

    const int ju = tid >> 3;
    const int bq = (tid & 7) * 4;
    const float* wpL = wfrag + w * 4096 + lane * 2;
    int cur = 0;

#pragma unroll 1
    for (int s = 0; s < Ss; s++) {
        const float* ht_c = g_ht[cur];
        float* ht_n = g_ht[cur ^ 1];

        float4 ho = __ldcg((const float4*)(ht_c + (j0 + ju) * Bb + b0 + bq));
        float xgv[4];
#pragma unroll
        for (int i = 0; i < 4; i++)
            xgv[i] = xg[(size_t)(s * Bb + b0 + bq + i) * Hh + j0 + ju];

        float acc[2][4][4];
#pragma unroll
        for (int mf = 0; mf < 2; mf++)
#pragma unroll
            for (int nf = 0; nf < 4; nf++)
#pragma unroll
                for (int e = 0; e < 4; e++) acc[mf][nf][e] = 0.f;

        float zacc[4] = {0.f, 0.f, 0.f, 0.f};
        float racc[4] = {0.f, 0.f, 0.f, 0.f};

        const float* ap = ht_c + (size_t)(w * 128 + t4) * Bb + b0 + g;

#pragma unroll 4
        for (int kf = 0; kf < 16; kf++) {
            float ar[8];
            const float* a = ap + kf * 1024;
            ar[0] = __ldcg(a + 0);
            ar[1] = __ldcg(a + 8);
            ar[2] = __ldcg(a + 16);
            ar[3] = __ldcg(a + 24);
            ar[4] = __ldcg(a + 512);
            ar[5] = __ldcg(a + 520);
            ar[6] = __ldcg(a + 528);
            ar[7] = __ldcg(a + 536);

            int kk = w * 128 + kf * 8 + t4;
            float wz0 = swz[kk], wz4 = swz[kk + 4];
            float wr0 = swr[kk], wr4 = swr[kk + 4];
            zacc[0] = fmaf(ar[0], wz0, fmaf(ar[4], wz4, zacc[0]));
            zacc[1] = fmaf(ar[1], wz0, fmaf(ar[5], wz4, zacc[1]));
            zacc[2] = fmaf(ar[2], wz0, fmaf(ar[6], wz4, zacc[2]));
            zacc[3] = fmaf(ar[3], wz0, fmaf(ar[7], wz4, zacc[3]));
            racc[0] = fmaf(ar[0], wr0, fmaf(ar[4], wr4, racc[0]));
            racc[1] = fmaf(ar[1], wr0, fmaf(ar[5], wr4, racc[1]));
            racc[2] = fmaf(ar[2], wr0, fmaf(ar[6], wr4, racc[2]));
            racc[3] = fmaf(ar[3], wr0, fmaf(ar[7], wr4, racc[3]));

            uint32_t at[8];
#pragma unroll
            for (int i = 0; i < 8; i++) at[i] = f2tf32(ar[i]);

#pragma unroll
            for (int nf = 0; nf < 4; nf++) {
                float2 bv = *(const float2*)(wpL + kf * 256 + nf * 64);
                uint32_t bx = __float_as_uint(bv.x);
                uint32_t by = __float_as_uint(bv.y);
                mma_tf32(acc[0][nf], at[0], at[1], at[4], at[5], bx, by);
                mma_tf32(acc[1][nf], at[2], at[3], at[6], at[7], bx, by);
            }
        }

        {
            float* rp = red + w * 1152;
#pragma unroll
            for (int mf = 0; mf < 2; mf++)
#pragma unroll
                for (int nf = 0; nf < 4; nf++) {
                    int jl = nf * 8 + 2 * t4;
                    int bl = mf * 16 + g;
                    rp[jl * 36 + bl]           = acc[mf][nf][0];
                    rp[(jl + 1) * 36 + bl]     = acc[mf][nf][1];
                    rp[jl * 36 + bl + 8]       = acc[mf][nf][2];
                    rp[(jl + 1) * 36 + bl + 8] = acc[mf][nf][3];
                }
        }
#pragma unroll
        for (int i = 0; i < 4; i++) {
            zacc[i] += __shfl_xor_sync(0xffffffffu, zacc[i], 1);
            zacc[i] += __shfl_xor_sync(0xffffffffu, zacc[i], 2);
            racc[i] += __shfl_xor_sync(0xffffffffu, racc[i], 1);
            racc[i] += __shfl_xor_sync(0xffffffffu, racc[i], 2);
        }
        if (t4 == 0) {
            zred[w * 32 + g]      = zacc[0];
            zred[w * 32 + g + 8]  = zacc[1];
            zred[w * 32 + g + 16] = zacc[2];
            zred[w * 32 + g + 24] = zacc[3];
            rred[w * 32 + g]      = racc[0];
            rred[w * 32 + g + 8]  = racc[1];
            rred[w * 32 + g + 16] = racc[2];
            rred[w * 32 + g + 24] = racc[3];
        }
        __syncthreads();
        if (tid < 32) {
            float zs = 0.f, rs = 0.f;
#pragma unroll
            for (int ww = 0; ww < 8; ww++) { zs += zred[ww * 32 + tid]; rs += rred[ww * 32 + tid]; }
            float zval = xz[s * Bb + b0 + tid] + zs + bz;
            float rval = xr[s * Bb + b0 + tid] + rs;
            zv[tid] = 1.f / (1.f + expf(-zval));
            rv[tid] = 1.f / (1.f + expf(-rval));
        }
        __syncthreads();

        float m0 = 0.f, m1 = 0.f, m2 = 0.f, m3 = 0.f;
#pragma unroll
        for (int ww = 0; ww < 8; ww++) {
            float4 p = *(const float4*)(red + ww * 1152 + ju * 36 + bq);
            m0 += p.x; m1 += p.y; m2 += p.z; m3 += p.w;
        }
        float mm[4] = {m0, m1, m2, m3};
        float hof[4] = {ho.x, ho.y, ho.z, ho.w};
        float hn[4];
#pragma unroll
        for (int i = 0; i < 4; i++) {
            int bb = b0 + bq + i;
            float gg = tanhf(xgv[i] + rv[bq + i] * mm[i] + bg[ju]);
            float zz = zv[bq + i];
            float v = zz * hof[i] + (1.f - zz) * gg;
            hn[i] = v;
            hs[(size_t)(s * Bb + bb) * Hh + j0 + ju] = v;
        }
        __stcg((float4*)(ht_n + (j0 + ju) * Bb + b0 + bq),
               make_float4(hn[0], hn[1], hn[2], hn[3]));
        cur ^= 1;
        grid_barrier();
    }

    const float* ht_c = g_ht[cur];
#pragma unroll
    for (int i = 0; i < 4; i++)
        hTl[(size_t)(b0 + bq + i) * (2 * Hh) + j0 + ju] =
            __ldcg(ht_c + (j0 + ju) * Bb + b0 + bq + i);
}

// ------------------------- launcher -------------------------------------------
extern "C" void kernel_launch(void* const* d_in, const int* in_sizes, int n_in,
                              void* d_out, int out_size) {
    (void)in_sizes; (void)n_in; (void)out_size;

    const float* x    = (const float*)d_in[0];
    const float* h0   = (const float*)d_in[1];
    const float* Wxz0 = (const float*)d_in[2];
    const float* Whz0 = (const float*)d_in[3];
    const float* bhz0 = (const float*)d_in[4];
    const float* Wxr0 = (const float*)d_in[5];
    const float* bxr0 = (const float*)d_in[6];
    const float* Whr0 = (const float*)d_in[7];
    const float* Wxg0 = (const float*)d_in[8];
    const float* Whg0 = (const float*)d_in[9];
    const float* bhg0 = (const float*)d_in[10];
    const float* Wxz1 = (const float*)d_in[11];
    const float* Whz1 = (const float*)d_in[12];
    const float* bhz1 = (const float*)d_in[13];
    const float* Wxr1 = (const float*)d_in[14];
    const float* bxr1 = (const float*)d_in[15];
    const float* Whr1 = (const float*)d_in[16];
    const float* Wxg1 = (const float*)d_in[17];
    const float* Whg1 = (const float*)d_in[18];
    const float* bhg1 = (const float*)d_in[19];
    const float* Why  = (const float*)d_in[20];
    const float* bhy  = (const float*)d_in[21];

    float* out   = (float*)d_out;
    float* out_y = out;                                  // (B,S,O)
    float* out_h = out + (size_t)Bb * Ss * Oo;           // (B,2,H)

    float *xzp, *xrp, *xgp, *hsp;
    cudaGetSymbolAddress((void**)&xzp, g_xz);
    cudaGetSymbolAddress((void**)&xrp, g_xr);
    cudaGetSymbolAddress((void**)&xgp, g_xg);
    cudaGetSymbolAddress((void**)&hsp, g_hs);

    cudaFuncSetAttribute(gru_scan, cudaFuncAttributeMaxDynamicSharedMemorySize,
                         SCAN_SMEM_BYTES);
    cudaFuncSetAttribute(wgemm_tf32<0>, cudaFuncAttributeMaxDynamicSharedMemorySize,
                         WG_SMEM_BYTES);
    cudaFuncSetAttribute(wgemm_tf32<1>, cudaFuncAttributeMaxDynamicSharedMemorySize,
                         WG_SMEM_BYTES);

    const int M = Ss * Bb;                // 32768
    dim3 gemmBlk(256);
    dim3 gemmGridH(M / 128, Hh / 128);    // (256, 8)
    dim3 gemmGridO(M / 128, Oo / 128);    // (256, 2)
    int projBlocks = M / 8;

    // ----- layer 0 -----
    proj_zr<<<projBlocks, 256>>>(x, Wxz0, Wxr0, bxr0, xzp, xrp, Ii, 1);
    wgemm_tf32<0><<<gemmGridH, gemmBlk, WG_SMEM_BYTES>>>(x, Wxg0, xgp, Hh, Ii, 1, nullptr);
    gru_scan<<<NBLK, 256, SCAN_SMEM_BYTES>>>(
        xzp, xrp, xgp, Whz0, Whr0, Whg0, bhz0, bhg0,
        h0 + 0 * Hh, hsp, out_h + 0 * Hh);

    // ----- layer 1 -----
    proj_zr<<<projBlocks, 256>>>(hsp, Wxz1, Wxr1, bxr1, xzp, xrp, Hh, 0);
    wgemm_tf32<0><<<gemmGridH, gemmBlk, WG_SMEM_BYTES>>>(hsp, Wxg1, xgp, Hh, Hh, 0, nullptr);
    gru_scan<<<NBLK, 256, SCAN_SMEM_BYTES>>>(
        xzp, xrp, xgp, Whz1, Whr1, Whg1, bhz1, bhg1,
        h0 + 1 * Hh, hsp, out_h + 1 * Hh);

    // ----- output head: sigmoid(hs1 @ Why^T + bhy) -> (B,S,O) -----
    wgemm_tf32<1><<<gemmGridO, gemmBlk, WG_SMEM_BYTES>>>(hsp, Why, out_y, Oo, Hh, 0, bhy);
}

// round 13
// speedup vs baseline: 2.7707x; 1.1511x over previous
#include <cuda_runtime.h>
#include <math.h>
#include <stdint.h>
#include <stddef.h>

#define Bb 128
#define Ss 256
#define Ii 256
#define Hh 1024
#define Oo 256
#define NBLK 128

// ------------------------- device scratch (no allocations allowed) -------------
__device__ float g_xz[Ss * Bb];
__device__ float g_xr[Ss * Bb];
__device__ float g_xg[(size_t)Ss * Bb * Hh];   // 128 MB
__device__ float g_hs[(size_t)Ss * Bb * Hh];   // 128 MB
__device__ float g_ht[2][Hh * Bb];             // hidden state, k-major [k][b], dbl buf
__device__ unsigned g_bar_count;
__device__ volatile unsigned g_bar_gen;

// ------------------------- grid barrier (all NBLK CTAs resident) ---------------
__device__ __forceinline__ void grid_barrier() {
    __syncthreads();
    if (threadIdx.x == 0) {
        __threadfence();
        unsigned gen = g_bar_gen;
        unsigned t = atomicAdd(&g_bar_count, 1u);
        if (t == gridDim.x - 1) {
            g_bar_count = 0;
            __threadfence();
            g_bar_gen = gen + 1u;
        } else {
            while (g_bar_gen == gen) { __nanosleep(32); }
        }
        __threadfence();
    }
    __syncthreads();
}

// ------------------------- tf32 / mma / cp.async helpers ------------------------
__device__ __forceinline__ uint32_t f2tf32(float v) {
    uint32_t u;
    asm("cvt.rna.tf32.f32 %0, %1;" : "=r"(u) : "f"(v));
    return u;
}
__device__ __forceinline__ void mma_tf32(float* d,
    uint32_t a0, uint32_t a1, uint32_t a2, uint32_t a3,
    uint32_t b0, uint32_t b1)
{
    asm volatile(
        "mma.sync.aligned.m16n8k8.row.col.f32.tf32.tf32.f32 "
        "{%0,%1,%2,%3}, {%4,%5,%6,%7}, {%8,%9}, {%0,%1,%2,%3};"
        : "+f"(d[0]), "+f"(d[1]), "+f"(d[2]), "+f"(d[3])
        : "r"(a0), "r"(a1), "r"(a2), "r"(a3), "r"(b0), "r"(b1));
}
__device__ __forceinline__ void cp_async16(uint32_t saddr, const void* gaddr) {
    asm volatile("cp.async.cg.shared.global [%0], [%1], 16;"
                 :: "r"(saddr), "l"(gaddr));
}
__device__ __forceinline__ void cp_commit() {
    asm volatile("cp.async.commit_group;");
}
__device__ __forceinline__ void cp_wait1() {
    asm volatile("cp.async.wait_group 1;");
}
__device__ __forceinline__ void cp_wait0() {
    asm volatile("cp.async.wait_group 0;");
}
__device__ __forceinline__ float sigf(float v) {
    return 1.f / (1.f + expf(-v));
}

// ------------------------- scalar-gate projections ----------------------------
__global__ void __launch_bounds__(256) proj_zr(
    const float* __restrict__ A, const float* __restrict__ Wxz,
    const float* __restrict__ Wxr, const float* __restrict__ bxr,
    float* __restrict__ xz, float* __restrict__ xr, int K, int amode)
{
    int warp = blockIdx.x * (blockDim.x >> 5) + (threadIdx.x >> 5);
    int lane = threadIdx.x & 31;
    const float* row;
    if (amode) {
        int s = warp >> 7, b = warp & 127;
        row = A + ((size_t)b * Ss + s) * K;
    } else {
        row = A + (size_t)warp * K;
    }
    float az = 0.f, ar = 0.f;
    for (int k = lane; k < K; k += 32) {
        float v = row[k];
        az = fmaf(v, Wxz[k], az);
        ar = fmaf(v, Wxr[k], ar);
    }
#pragma unroll
    for (int d = 16; d; d >>= 1) {
        az += __shfl_down_sync(0xffffffffu, az, d);
        ar += __shfl_down_sync(0xffffffffu, ar, d);
    }
    if (lane == 0) { xz[warp] = az; xr[warp] = ar + bxr[0]; }
}

// ------------------------- cp.async-pipelined tf32 GEMM v4 ----------------------
// C[r,n] = sum_k Arow(r)[k] * Bw[n,k]. 128x128 tile, kstep 32, 3-stage cp.async
// ring, plain [row][36] smem tiles (pad 36 -> conflict-free fragment LDS.32),
// tf32 cvt at fragment load. 512 threads, 16 warps, warp tile 32m x 32n.
// EPI==0: C row-major. EPI==1: sigmoid(v + bias[n]) scattered to (B,S,N).
#define GD 36
#define GA_FLOATS (128 * GD)            // 4608
#define G_STAGE   (2 * GA_FLOATS)       // 9216 floats (A + B)
#define G_DEPTH   3
#define WG_SMEM_BYTES (G_DEPTH * G_STAGE * 4)   // 110592 B

template <int EPI>
__global__ void __launch_bounds__(512) wgemm_tf32(
    const float* __restrict__ A, const float* __restrict__ Bw,
    float* __restrict__ C, int N, int K, int amode,
    const float* __restrict__ bias)
{
    extern __shared__ float sm[];

    const int tid = threadIdx.x;
    const int m0 = blockIdx.x * 128;
    const int n0 = blockIdx.y * 128;
    const int lane = tid & 31;
    const int w  = tid >> 5;            // 0..15
    const int wr = w & 3;               // m offset wr*32
    const int wc = w >> 2;              // n offset wc*32
    const int g  = lane >> 2, t4 = lane & 3;

    // ---- staging: thread owns rows r0,r0+64 (A and B), float4 col c4.
    // 8 consecutive threads cover 128B of ONE row -> fully coalesced.
    const int r0 = tid >> 3;            // 0..63
    const int r1 = r0 + 64;
    const int c4 = (tid & 7) * 4;

    const float* aR0;
    const float* aR1;
    {
        int ar0 = m0 + r0, ar1 = m0 + r1;
        if (amode) {
            aR0 = A + ((size_t)(ar0 & 127) * Ss + (ar0 >> 7)) * K;
            aR1 = A + ((size_t)(ar1 & 127) * Ss + (ar1 >> 7)) * K;
        } else {
            aR0 = A + (size_t)ar0 * K;
            aR1 = A + (size_t)ar1 * K;
        }
    }
    const float* bR0 = Bw + (size_t)(n0 + r0) * K;
    const float* bR1 = Bw + (size_t)(n0 + r1) * K;

    const uint32_t sbase = (uint32_t)__cvta_generic_to_shared(sm);
    const uint32_t sa0 = (uint32_t)((r0 * GD + c4) * 4);
    const uint32_t sa1 = (uint32_t)((r1 * GD + c4) * 4);
    const uint32_t sb0 = (uint32_t)((GA_FLOATS + r0 * GD + c4) * 4);
    const uint32_t sb1 = (uint32_t)((GA_FLOATS + r1 * GD + c4) * 4);

    float acc[2][4][4];
#pragma unroll
    for (int i = 0; i < 2; i++)
#pragma unroll
        for (int j = 0; j < 4; j++)
#pragma unroll
            for (int e = 0; e < 4; e++) acc[i][j][e] = 0.f;

    const int nstages = K / 32;

    // prologue: stages 0,1 in flight
#pragma unroll
    for (int p = 0; p < 2; p++) {
        uint32_t base = sbase + (uint32_t)(p * G_STAGE * 4);
        int k0 = p * 32;
        cp_async16(base + sa0, aR0 + k0 + c4);
        cp_async16(base + sa1, aR1 + k0 + c4);
        cp_async16(base + sb0, bR0 + k0 + c4);
        cp_async16(base + sb1, bR1 + k0 + c4);
        cp_commit();
    }

#pragma unroll 1
    for (int t = 0; t < nstages; t++) {
        if (t < nstages - 1) cp_wait1(); else cp_wait0();
        __syncthreads();

        // issue stage t+2 into ring slot (t+2)%3 (readers of that slot done)
        if (t + 2 < nstages) {
            uint32_t base = sbase + (uint32_t)(((t + 2) % G_DEPTH) * G_STAGE * 4);
            int k0 = (t + 2) * 32;
            cp_async16(base + sa0, aR0 + k0 + c4);
            cp_async16(base + sa1, aR1 + k0 + c4);
            cp_async16(base + sb0, bR0 + k0 + c4);
            cp_async16(base + sb1, bR1 + k0 + c4);
            cp_commit();
        } else {
            cp_commit();   // keep group count aligned with wait_group bookkeeping
        }

        const float* sa = sm + (t % G_DEPTH) * G_STAGE;
        const float* sbB = sa + GA_FLOATS;
        const float* saW = sa + (wr * 32) * GD;
        const float* sbW = sbB + (wc * 32) * GD;

#pragma unroll
        for (int kf = 0; kf < 4; kf++) {
            uint32_t a[2][4];
#pragma unroll
            for (int mf = 0; mf < 2; mf++) {
                const float* p = saW + (mf * 16 + g) * GD + kf * 8 + t4;
                a[mf][0] = f2tf32(p[0]);
                a[mf][1] = f2tf32(p[8 * GD]);
                a[mf][2] = f2tf32(p[4]);
                a[mf][3] = f2tf32(p[8 * GD + 4]);
            }
#pragma unroll
            for (int nf = 0; nf < 4; nf++) {
                const float* q = sbW + (nf * 8 + g) * GD + kf * 8 + t4;
                uint32_t b0 = f2tf32(q[0]);
                uint32_t b1 = f2tf32(q[4]);
                mma_tf32(acc[0][nf], a[0][0], a[0][1], a[0][2], a[0][3], b0, b1);
                mma_tf32(acc[1][nf], a[1][0], a[1][1], a[1][2], a[1][3], b0, b1);
            }
        }
    }

    // ---- epilogue: c-frags straight to gmem (STG.64)
    if (EPI == 0) {
#pragma unroll
        for (int mf = 0; mf < 2; mf++) {
            int mr = m0 + wr * 32 + mf * 16 + g;
#pragma unroll
            for (int nf = 0; nf < 4; nf++) {
                int nb = n0 + wc * 32 + nf * 8 + 2 * t4;
                *(float2*)&C[(size_t)mr * N + nb] =
                    make_float2(acc[mf][nf][0], acc[mf][nf][1]);
                *(float2*)&C[(size_t)(mr + 8) * N + nb] =
                    make_float2(acc[mf][nf][2], acc[mf][nf][3]);
            }
        }
    } else {
        const int sIdx = m0 >> 7;     // s constant within M-tile; b = m-local
#pragma unroll
        for (int mf = 0; mf < 2; mf++) {
            int bl = wr * 32 + mf * 16 + g;
#pragma unroll
            for (int nf = 0; nf < 4; nf++) {
                int nb = n0 + wc * 32 + nf * 8 + 2 * t4;
                float bs0 = bias[nb], bs1 = bias[nb + 1];
                *(float2*)&C[((size_t)bl * Ss + sIdx) * N + nb] =
                    make_float2(sigf(acc[mf][nf][0] + bs0),
                                sigf(acc[mf][nf][1] + bs1));
                *(float2*)&C[((size_t)(bl + 8) * Ss + sIdx) * N + nb] =
                    make_float2(sigf(acc[mf][nf][2] + bs0),
                                sigf(acc[mf][nf][3] + bs1));
            }
        }
    }
}

// ------------------------- persistent GRU scan (r11 WIN, unchanged) ------------
#define SCAN_SMEM_FLOATS (32*Hh + Hh + Hh + 8*1152 + 256 + 256 + 32 + 32 + 32)
#define SCAN_SMEM_BYTES  (SCAN_SMEM_FLOATS * 4)

__global__ void __launch_bounds__(256) gru_scan(
    const float* __restrict__ xz, const float* __restrict__ xr,
    const float* __restrict__ xg,
    const float* __restrict__ Whz, const float* __restrict__ Whr,
    const float* __restrict__ Whg,
    const float* __restrict__ bhz, const float* __restrict__ bhg,
    const float* __restrict__ h0l,
    float* __restrict__ hs, float* __restrict__ hTl)
{
    extern __shared__ float smem[];
    float* wfrag = smem;
    float* swz   = wfrag + 32 * Hh;
    float* swr   = swz + Hh;
    float* red   = swr + Hh;
    float* zred  = red + 8 * 1152;
    float* rred  = zred + 256;
    float* zv    = rred + 256;
    float* rv    = zv + 32;
    float* bg    = rv + 32;

    const int tid  = threadIdx.x;
    const int w    = tid >> 5, lane = tid & 31;
    const int g    = lane >> 2, t4 = lane & 3;
    const int bt   = blockIdx.x >> 5, nt = blockIdx.x & 31;
    const int b0   = bt * 32, j0 = nt * 32;

    for (int idx = tid; idx < 32 * Hh; idx += 256) {
        int c  = idx & 1;
        int l  = (idx >> 1) & 31;
        int nf = (idx >> 6) & 3;
        int wk = idx >> 8;
        int k  = wk * 8 + (l & 3) + c * 4;
        int j  = j0 + nf * 8 + (l >> 2);
        wfrag[idx] = __uint_as_float(f2tf32(Whg[(size_t)j * Hh + k]));
    }
    for (int idx = tid; idx < Hh; idx += 256) { swz[idx] = Whz[idx]; swr[idx] = Whr[idx]; }
    if (tid < 32) bg[tid] = bhg[j0 + tid];
    const float bz = bhz[0];

    for (int idx = blockIdx.x * 256 + tid; idx < Bb * Hh; idx += NBLK * 256) {
        int b = idx & 127, k = idx >> 7;
        g_ht[0][idx] = h0l[(size_t)b * (2 * Hh) + k];
    }
    grid_barrier();

    const int ju = tid >> 3;
    const int bq = (tid & 7) * 4;
    const float* wpL = wfrag + w * 4096 + lane * 2;
    int cur = 0;

#pragma unroll 1
    for (int s = 0; s < Ss; s++) {
        const float* ht_c = g_ht[cur];
        float* ht_n = g_ht[cur ^ 1];

        float4 ho = __ldcg((const float4*)(ht_c + (j0 + ju) * Bb + b0 + bq));
        float xgv[4];
#pragma unroll
        for (int i = 0; i < 4; i++)
            xgv[i] = xg[(size_t)(s * Bb + b0 + bq + i) * Hh + j0 + ju];

        float acc[2][4][4];
#pragma unroll
        for (int mf = 0; mf < 2; mf++)
#pragma unroll
            for (int nf = 0; nf < 4; nf++)
#pragma unroll
                for (int e = 0; e < 4; e++) acc[mf][nf][e] = 0.f;

        float zacc[4] = {0.f, 0.f, 0.f, 0.f};
        float racc[4] = {0.f, 0.f, 0.f, 0.f};

        const float* ap = ht_c + (size_t)(w * 128 + t4) * Bb + b0 + g;

#pragma unroll 4
        for (int kf = 0; kf < 16; kf++) {
            float ar[8];
            const float* a = ap + kf * 1024;
            ar[0] = __ldcg(a + 0);
            ar[1] = __ldcg(a + 8);
            ar[2] = __ldcg(a + 16);
            ar[3] = __ldcg(a + 24);
            ar[4] = __ldcg(a + 512);
            ar[5] = __ldcg(a + 520);
            ar[6] = __ldcg(a + 528);
            ar[7] = __ldcg(a + 536);

            int kk = w * 128 + kf * 8 + t4;
            float wz0 = swz[kk], wz4 = swz[kk + 4];
            float wr0 = swr[kk], wr4 = swr[kk + 4];
            zacc[0] = fmaf(ar[0], wz0, fmaf(ar[4], wz4, zacc[0]));
            zacc[1] = fmaf(ar[1], wz0, fmaf(ar[5], wz4, zacc[1]));
            zacc[2] = fmaf(ar[2], wz0, fmaf(ar[6], wz4, zacc[2]));
            zacc[3] = fmaf(ar[3], wz0, fmaf(ar[7], wz4, zacc[3]));
            racc[0] = fmaf(ar[0], wr0, fmaf(ar[4], wr4, racc[0]));
            racc[1] = fmaf(ar[1], wr0, fmaf(ar[5], wr4, racc[1]));
            racc[2] = fmaf(ar[2], wr0, fmaf(ar[6], wr4, racc[2]));
            racc[3] = fmaf(ar[3], wr0, fmaf(ar[7], wr4, racc[3]));

            uint32_t at[8];
#pragma unroll
            for (int i = 0; i < 8; i++) at[i] = f2tf32(ar[i]);

#pragma unroll
            for (int nf = 0; nf < 4; nf++) {
                float2 bv = *(const float2*)(wpL + kf * 256 + nf * 64);
                uint32_t bx = __float_as_uint(bv.x);
                uint32_t by = __float_as_uint(bv.y);
                mma_tf32(acc[0][nf], at[0], at[1], at[4], at[5], bx, by);
                mma_tf32(acc[1][nf], at[2], at[3], at[6], at[7], bx, by);
            }
        }

        {
            float* rp = red + w * 1152;
#pragma unroll
            for (int mf = 0; mf < 2; mf++)
#pragma unroll
                for (int nf = 0; nf < 4; nf++) {
                    int jl = nf * 8 + 2 * t4;
                    int bl = mf * 16 + g;
                    rp[jl * 36 + bl]           = acc[mf][nf][0];
                    rp[(jl + 1) * 36 + bl]     = acc[mf][nf][1];
                    rp[jl * 36 + bl + 8]       = acc[mf][nf][2];
                    rp[(jl + 1) * 36 + bl + 8] = acc[mf][nf][3];
                }
        }
#pragma unroll
        for (int i = 0; i < 4; i++) {
            zacc[i] += __shfl_xor_sync(0xffffffffu, zacc[i], 1);
            zacc[i] += __shfl_xor_sync(0xffffffffu, zacc[i], 2);
            racc[i] += __shfl_xor_sync(0xffffffffu, racc[i], 1);
            racc[i] += __shfl_xor_sync(0xffffffffu, racc[i], 2);
        }
        if (t4 == 0) {
            zred[w * 32 + g]      = zacc[0];
            zred[w * 32 + g + 8]  = zacc[1];
            zred[w * 32 + g + 16] = zacc[2];
            zred[w * 32 + g + 24] = zacc[3];
            rred[w * 32 + g]      = racc[0];
            rred[w * 32 + g + 8]  = racc[1];
            rred[w * 32 + g + 16] = racc[2];
            rred[w * 32 + g + 24] = racc[3];
        }
        __syncthreads();
        if (tid < 32) {
            float zs = 0.f, rs = 0.f;
#pragma unroll
            for (int ww = 0; ww < 8; ww++) { zs += zred[ww * 32 + tid]; rs += rred[ww * 32 + tid]; }
            float zval = xz[s * Bb + b0 + tid] + zs + bz;
            float rval = xr[s * Bb + b0 + tid] + rs;
            zv[tid] = 1.f / (1.f + expf(-zval));
            rv[tid] = 1.f / (1.f + expf(-rval));
        }
        __syncthreads();

        float m0 = 0.f, m1 = 0.f, m2 = 0.f, m3 = 0.f;
#pragma unroll
        for (int ww = 0; ww < 8; ww++) {
            float4 p = *(const float4*)(red + ww * 1152 + ju * 36 + bq);
            m0 += p.x; m1 += p.y; m2 += p.z; m3 += p.w;
        }
        float mm[4] = {m0, m1, m2, m3};
        float hof[4] = {ho.x, ho.y, ho.z, ho.w};
        float hn[4];
#pragma unroll
        for (int i = 0; i < 4; i++) {
            int bb = b0 + bq + i;
            float gg = tanhf(xgv[i] + rv[bq + i] * mm[i] + bg[ju]);
            float zz = zv[bq + i];
            float v = zz * hof[i] + (1.f - zz) * gg;
            hn[i] = v;
            hs[(size_t)(s * Bb + bb) * Hh + j0 + ju] = v;
        }
        __stcg((float4*)(ht_n + (j0 + ju) * Bb + b0 + bq),
               make_float4(hn[0], hn[1], hn[2], hn[3]));
        cur ^= 1;
        grid_barrier();
    }

    const float* ht_c = g_ht[cur];
#pragma unroll
    for (int i = 0; i < 4; i++)
        hTl[(size_t)(b0 + bq + i) * (2 * Hh) + j0 + ju] =
            __ldcg(ht_c + (j0 + ju) * Bb + b0 + bq + i);
}

// ------------------------- launcher -------------------------------------------
extern "C" void kernel_launch(void* const* d_in, const int* in_sizes, int n_in,
                              void* d_out, int out_size) {
    (void)in_sizes; (void)n_in; (void)out_size;

    const float* x    = (const float*)d_in[0];
    const float* h0   = (const float*)d_in[1];
    const float* Wxz0 = (const float*)d_in[2];
    const float* Whz0 = (const float*)d_in[3];
    const float* bhz0 = (const float*)d_in[4];
    const float* Wxr0 = (const float*)d_in[5];
    const float* bxr0 = (const float*)d_in[6];
    const float* Whr0 = (const float*)d_in[7];
    const float* Wxg0 = (const float*)d_in[8];
    const float* Whg0 = (const float*)d_in[9];
    const float* bhg0 = (const float*)d_in[10];
    const float* Wxz1 = (const float*)d_in[11];
    const float* Whz1 = (const float*)d_in[12];
    const float* bhz1 = (const float*)d_in[13];
    const float* Wxr1 = (const float*)d_in[14];
    const float* bxr1 = (const float*)d_in[15];
    const float* Whr1 = (const float*)d_in[16];
    const float* Wxg1 = (const float*)d_in[17];
    const float* Whg1 = (const float*)d_in[18];
    const float* bhg1 = (const float*)d_in[19];
    const float* Why  = (const float*)d_in[20];
    const float* bhy  = (const float*)d_in[21];

    float* out   = (float*)d_out;
    float* out_y = out;                                  // (B,S,O)
    float* out_h = out + (size_t)Bb * Ss * Oo;           // (B,2,H)

    float *xzp, *xrp, *xgp, *hsp;
    cudaGetSymbolAddress((void**)&xzp, g_xz);
    cudaGetSymbolAddress((void**)&xrp, g_xr);
    cudaGetSymbolAddress((void**)&xgp, g_xg);
    cudaGetSymbolAddress((void**)&hsp, g_hs);

    cudaFuncSetAttribute(gru_scan, cudaFuncAttributeMaxDynamicSharedMemorySize,
                         SCAN_SMEM_BYTES);
    cudaFuncSetAttribute(wgemm_tf32<0>, cudaFuncAttributeMaxDynamicSharedMemorySize,
                         WG_SMEM_BYTES);
    cudaFuncSetAttribute(wgemm_tf32<1>, cudaFuncAttributeMaxDynamicSharedMemorySize,
                         WG_SMEM_BYTES);

    const int M = Ss * Bb;                // 32768
    dim3 gemmBlk(512);
    dim3 gemmGridH(M / 128, Hh / 128);    // (256, 8)
    dim3 gemmGridO(M / 128, Oo / 128);    // (256, 2)
    int projBlocks = M / 8;

    // ----- layer 0 -----
    proj_zr<<<projBlocks, 256>>>(x, Wxz0, Wxr0, bxr0, xzp, xrp, Ii, 1);
    wgemm_tf32<0><<<gemmGridH, gemmBlk, WG_SMEM_BYTES>>>(x, Wxg0, xgp, Hh, Ii, 1, nullptr);
    gru_scan<<<NBLK, 256, SCAN_SMEM_BYTES>>>(
        xzp, xrp, xgp, Whz0, Whr0, Whg0, bhz0, bhg0,
        h0 + 0 * Hh, hsp, out_h + 0 * Hh);

    // ----- layer 1 -----
    proj_zr<<<projBlocks, 256>>>(hsp, Wxz1, Wxr1, bxr1, xzp, xrp, Hh, 0);
    wgemm_tf32<0><<<gemmGridH, gemmBlk, WG_SMEM_BYTES>>>(hsp, Wxg1, xgp, Hh, Hh, 0, nullptr);
    gru_scan<<<NBLK, 256, SCAN_SMEM_BYTES>>>(
        xzp, xrp, xgp, Whz1, Whr1, Whg1, bhz1, bhg1,
        h0 + 1 * Hh, hsp, out_h + 1 * Hh);

    // ----- output head: sigmoid(hs1 @ Why^T + bhy) -> (B,S,O) -----
    wgemm_tf32<1><<<gemmGridO, gemmBlk, WG_SMEM_BYTES>>>(hsp, Why, out_y, Oo, Hh, 0, bhy);
}